// round 6
// baseline (speedup 1.0000x reference)
#include <cuda_runtime.h>
#include <cuda_bf16.h>
#include <math.h>

// ---------------------------------------------------------------------------
// WarpNet — Round 6: HMMA implicit-GEMM convs, fed properly.
//   512 thr/CTA (16 warps, 4m x 4n), warp tile M=32 x N=32, K chunks of 32.
//   A (weights, frag-ordered) via cp.async double buffer -> swizzled LDS.128.
//   B built per tap from conflict-free staging into 160B-padded ldmatrix tiles.
//   3-term bf16 emulation: D ~= Ahi*Bhi + Alo*Bhi + Ahi*Blo.
// ---------------------------------------------------------------------------

#define NIMG   4
#define CIN    512
#define HW     64
#define C1     256
#define C2     128
#define NCLS   124
#define NPAIR  2
#define KTOT   4608
#define X_ELEMS (2 * NCLS * HW * HW)
#define NCHUNK 144

typedef unsigned int u32;

// ---------------- scratch (device globals) -----------------------------------
__device__ float g_sbuf [NIMG * C1 * HW * HW];
__device__ float g_y2   [NPAIR * HW * HW];
__device__ float g_wgt  [25 * NPAIR * HW * HW];
__device__ float g_final[NPAIR * HW * HW * C1];
__device__ float g_WT   [256 * NCLS];
__device__ __align__(16) u32 g_Xpk[NIMG * CIN * HW * HW];   // bf16 hi|lo packed
__device__ __align__(16) u32 g_A1hi[C1 * KTOT / 2];         // frag-ordered weights
__device__ __align__(16) u32 g_A1lo[C1 * KTOT / 2];
__device__ __align__(16) u32 g_A2hi[C2 * KTOT / 2];
__device__ __align__(16) u32 g_A2lo[C2 * KTOT / 2];

// ---------------- helpers ------------------------------------------------------
__device__ __forceinline__ u32 smem_u32(const void* p) {
    u32 a;
    asm("{ .reg .u64 t; cvta.to.shared.u64 t, %1; cvt.u32.u64 %0, t; }"
        : "=r"(a) : "l"(p));
    return a;
}
__device__ __forceinline__ void ldmx2(u32& r0, u32& r1, u32 addr) {
    asm volatile("ldmatrix.sync.aligned.m8n8.x2.shared.b16 {%0,%1}, [%2];"
        : "=r"(r0), "=r"(r1) : "r"(addr));
}
__device__ __forceinline__ void lds128(u32* r, u32 addr) {
    asm volatile("ld.shared.v4.u32 {%0,%1,%2,%3}, [%4];"
        : "=r"(r[0]), "=r"(r[1]), "=r"(r[2]), "=r"(r[3]) : "r"(addr));
}
__device__ __forceinline__ void sts128(u32 addr, u32 a, u32 b, u32 c, u32 d) {
    asm volatile("st.shared.v4.b32 [%0], {%1,%2,%3,%4};"
        :: "r"(addr), "r"(a), "r"(b), "r"(c), "r"(d) : "memory");
}
__device__ __forceinline__ void mma_bf16(float* d, const u32* a, const u32* b) {
    asm volatile("mma.sync.aligned.m16n8k16.row.col.f32.bf16.bf16.f32 "
        "{%0,%1,%2,%3}, {%4,%5,%6,%7}, {%8,%9}, {%0,%1,%2,%3};"
        : "+f"(d[0]), "+f"(d[1]), "+f"(d[2]), "+f"(d[3])
        : "r"(a[0]), "r"(a[1]), "r"(a[2]), "r"(a[3]), "r"(b[0]), "r"(b[1]));
}
__device__ __forceinline__ void cp16(u32 daddr, const void* g) {
    asm volatile("cp.async.cg.shared.global [%0], [%1], 16;"
        :: "r"(daddr), "l"(g) : "memory");
}
#define CP_COMMIT() asm volatile("cp.async.commit_group;" ::: "memory")
#define CP_WAIT0()  asm volatile("cp.async.wait_group 0;" ::: "memory")

// ---------------- smem layout (bytes) -------------------------------------------
// staging: 32 ci x 265 u32 (4 rows x 66 cols + 1 pad) = 33920
// A: 2 buf x (2048 u32 hi + 2048 u32 lo) = 32768
// B: 2 buf x (10240 hi + 10240 lo) = 40960   (64 blocks x 160 B per tile)
#define OFF_STG  0
#define OFF_A    33920
#define OFF_B    (33920 + 32768)
#define B_TILE   10240
#define SMEM_SZ  (OFF_B + 40960)

// ---------------- prep kernels ---------------------------------------------------
__global__ void prep_x(const float* __restrict__ x)
{
    int i = blockIdx.x * 256 + threadIdx.x;
    float v = x[i];
    __nv_bfloat16 h = __float2bfloat16(v);
    __nv_bfloat16 l = __float2bfloat16(v - __bfloat162float(h));
    g_Xpk[i] = (u32)__bfloat16_as_ushort(h) | ((u32)__bfloat16_as_ushort(l) << 16);
}

// Weights -> frag order, lane-major within (blk, wm): i = blk*2048 + wm*512 + lane*16 + q
__global__ void prep_w(const float* __restrict__ W, u32* __restrict__ Ahi,
                       u32* __restrict__ Alo)
{
    int i = blockIdx.x * 256 + threadIdx.x;
    int q = i & 15, lane = (i >> 4) & 31, wm = (i >> 9) & 3, blk = i >> 11;
    int cz = blk / NCHUNK, c = blk - cz * NCHUNK;
    int kb = q >> 3, f = (q >> 2) & 1, reg = q & 3;
    int co = cz * 128 + wm * 32 + f * 16 + (lane >> 2) + (reg & 1) * 8;
    int k  = kb * 16 + 2 * (lane & 3) + (reg >> 1) * 8;
    int cib = c / 9, p = c - cib * 9;
    int ci = cib * 32 + k;
    float v0 = W[((size_t)co * 512 + ci    ) * 9 + p];
    float v1 = W[((size_t)co * 512 + ci + 1) * 9 + p];
    __nv_bfloat16 h0 = __float2bfloat16(v0);
    __nv_bfloat16 h1 = __float2bfloat16(v1);
    __nv_bfloat16 l0 = __float2bfloat16(v0 - __bfloat162float(h0));
    __nv_bfloat16 l1 = __float2bfloat16(v1 - __bfloat162float(h1));
    Ahi[i] = (u32)__bfloat16_as_ushort(h0) | ((u32)__bfloat16_as_ushort(h1) << 16);
    Alo[i] = (u32)__bfloat16_as_ushort(l0) | ((u32)__bfloat16_as_ushort(l1) << 16);
}

// ---------------- conv via mma.sync ------------------------------------------------
template<int COUT, bool TO_SBUF>
__global__ __launch_bounds__(512, 1)
void conv_mma(const u32* __restrict__ Ahi, const u32* __restrict__ Alo,
              const float* __restrict__ bg, const float* __restrict__ bb,
              const float* __restrict__ bm, const float* __restrict__ bv,
              float* __restrict__ out_ext)
{
    extern __shared__ char smem[];
    u32* stg = (u32*)smem;
    const u32 sb = smem_u32(smem);

    const int t   = threadIdx.x;
    const int l   = t & 31;
    const int wid = t >> 5;
    const int wm  = wid & 3;
    const int wn  = wid >> 2;
    const int h0  = blockIdx.x * 2;
    const int cz  = blockIdx.y;
    const int img = blockIdx.z;
    const int lsw = (l >> 1) & 3;       // A-swizzle selector

    float acc[2][4][4];
    #pragma unroll
    for (int f = 0; f < 2; ++f)
        #pragma unroll
        for (int nf = 0; nf < 4; ++nf)
            #pragma unroll
            for (int r = 0; r < 4; ++r) acc[f][nf][r] = 0.f;

    const u32* Xpk = g_Xpk + (size_t)img * CIN * HW * HW;
    const u32* Abh = Ahi + (size_t)cz * NCHUNK * 2048;
    const u32* Abl = Alo + (size_t)cz * NCHUNK * 2048;

    // cp.async dst (bytes): wm'*2048 + lane'*64 + swizzled-qb*16
    const int cp_lane = (t & 127) >> 2, cp_qb = t & 3;
    const u32 cp_dst = (u32)((t >> 7) * 2048 + cp_lane * 64 +
                             ((cp_qb ^ ((cp_lane >> 1) & 3)) << 4));

    // B build constants
    const int bn = t >> 2, ksb = t & 3;          // n 0..127, k-block 0..3
    const int br = bn >> 6, bw = bn & 63;
    const u32 st_addr = (u32)(((bn >> 3) * 4 + ksb) * 160 + (bn & 7) * 16);

    // issue A[0]
    {
        cp16(sb + OFF_A + cp_dst, Abh + t * 4);
        cp16(sb + OFF_A + 8192 + cp_dst, Abl + t * 4);
        CP_COMMIT();
    }

    int chunk = 0;
    for (int cib = 0; cib < 16; ++cib) {
        __syncthreads();   // staging WAR
        for (int e = t; e < 32 * 264; e += 512) {
            int ci  = e / 264;
            int rem = e - ci * 264;
            int row = rem / 66;
            int col = rem - row * 66;
            int gh  = h0 + row - 1;
            int gw  = col - 1;
            u32 v = 0;
            if ((unsigned)gh < 64u && (unsigned)gw < 64u)
                v = Xpk[((size_t)(cib * 32 + ci) * HW + gh) * HW + gw];
            stg[ci * 265 + rem] = v;
        }
        __syncthreads();

        for (int p = 0; p < 9; ++p, ++chunk) {
            const int buf = chunk & 1;
            const u32 bB = sb + OFF_B + (u32)(buf * 2 * B_TILE);
            const u32 bA = sb + OFF_A + (u32)(buf * 16384);

            // ---- build B (hi, lo) for this tap: conflict-free LDS + STS.128 ----
            {
                const u32* src = stg + (br + p / 3) * 66 + (bw + p % 3);
                u32 hw[4], lw[4];
                #pragma unroll
                for (int j = 0; j < 4; ++j) {
                    int k0 = ksb * 8 + 2 * j;
                    u32 v0 = src[(k0    ) * 265];
                    u32 v1 = src[(k0 + 1) * 265];
                    hw[j] = (v0 & 0xFFFFu) | (v1 << 16);
                    lw[j] = (v0 >> 16) | (v1 & 0xFFFF0000u);
                }
                sts128(bB + st_addr,          hw[0], hw[1], hw[2], hw[3]);
                sts128(bB + B_TILE + st_addr, lw[0], lw[1], lw[2], lw[3]);
            }

            CP_WAIT0();          // A[chunk] resident
            __syncthreads();     // B + A visible; prev chunk reads complete

            // prefetch A[chunk+1]
            if (chunk + 1 < NCHUNK) {
                const u32 nb = sb + OFF_A + (u32)(((chunk + 1) & 1) * 16384);
                cp16(nb + cp_dst, Abh + (size_t)(chunk + 1) * 2048 + t * 4);
                cp16(nb + 8192 + cp_dst, Abl + (size_t)(chunk + 1) * 2048 + t * 4);
                CP_COMMIT();
            }

            // ---- load A frags (swizzled LDS.128) ----
            u32 ah[16], al[16];
            #pragma unroll
            for (int qb2 = 0; qb2 < 4; ++qb2) {
                u32 a = bA + (u32)((wm * 512 + l * 16 + ((qb2 ^ lsw) << 2)) * 4);
                lds128(ah + qb2 * 4, a);
                lds128(al + qb2 * 4, a + 8192);
            }

            // ---- ldmatrix B + MMA ----
            #pragma unroll
            for (int kb = 0; kb < 2; ++kb) {
                #pragma unroll
                for (int nf = 0; nf < 4; ++nf) {
                    u32 bi = (u32)(((wn * 4 + nf) * 4 + kb * 2 + ((l >> 3) & 1)));
                    u32 a = bB + bi * 160 + (u32)((l & 7) * 16);
                    u32 bh[2], bl_[2];
                    ldmx2(bh[0], bh[1], a);
                    ldmx2(bl_[0], bl_[1], a + B_TILE);
                    #pragma unroll
                    for (int f = 0; f < 2; ++f) {
                        const u32* a_h = ah + kb * 8 + f * 4;
                        const u32* a_l = al + kb * 8 + f * 4;
                        mma_bf16(acc[f][nf], a_h, bh);
                        mma_bf16(acc[f][nf], a_l, bh);
                        mma_bf16(acc[f][nf], a_h, bl_);
                    }
                }
            }
        }
    }

    // ---- epilogue: BN + ReLU, NCHW ----
    float* op = TO_SBUF ? g_sbuf : out_ext;
    #pragma unroll
    for (int f = 0; f < 2; ++f) {
        int co0 = cz * 128 + wm * 32 + f * 16 + (l >> 2);
        float sc0 = bg[co0] * rsqrtf(bv[co0] + 1e-5f);
        float bi0 = bb[co0] - bm[co0] * sc0;
        float sc1 = bg[co0 + 8] * rsqrtf(bv[co0 + 8] + 1e-5f);
        float bi1 = bb[co0 + 8] - bm[co0 + 8] * sc1;
        #pragma unroll
        for (int nf = 0; nf < 4; ++nf) {
            int n0 = wn * 32 + nf * 8 + 2 * (l & 3);
            int row = h0 + (n0 >> 6), w = n0 & 63;
            float v0 = fmaf(acc[f][nf][0], sc0, bi0);
            float v1 = fmaf(acc[f][nf][1], sc0, bi0);
            float v2 = fmaf(acc[f][nf][2], sc1, bi1);
            float v3 = fmaf(acc[f][nf][3], sc1, bi1);
            *(float2*)(op + (((size_t)img * COUT + co0    ) * HW + row) * HW + w) =
                make_float2(v0 > 0.f ? v0 : 0.f, v1 > 0.f ? v1 : 0.f);
            *(float2*)(op + (((size_t)img * COUT + co0 + 8) * HW + row) * HW + w) =
                make_float2(v2 > 0.f ? v2 : 0.f, v3 > 0.f ? v3 : 0.f);
        }
    }
}

// ---------------------------------------------------------------------------
__global__ void y2_kernel(const float* __restrict__ ce2)
{
    int nb = blockIdx.x;
    int n = nb >> 6, h = nb & 63, w = threadIdx.x;
    const float* p = ce2 + ((size_t)n * C2 * HW + h) * HW + w;
    float acc = 0.f;
    for (int c = 0; c < C2; ++c) {
        float v = p[(size_t)c * HW * HW];
        acc = fmaf(v, v, acc);
    }
    g_y2[(n * HW + h) * HW + w] = acc;
}

// ---------------------------------------------------------------------------
__global__ __launch_bounds__(512)
void wgt_kernel(const float* __restrict__ ce2)
{
    __shared__ float s_oth[8][5][68];
    __shared__ float s_acc[26][4][64];

    int nb = blockIdx.x;
    int n = nb >> 6, h = nb & 63;
    int t = threadIdx.x;
    int cg = t >> 6, w = t & 63;

    float acc[25];
    #pragma unroll
    for (int o = 0; o < 25; ++o) acc[o] = 0.f;
    float x2 = 0.f;

    const float* oth = ce2 + (size_t)n       * C2 * HW * HW;
    const float* c2  = ce2 + (size_t)(2 + n) * C2 * HW * HW;

    for (int c0 = 0; c0 < C2; c0 += 8) {
        __syncthreads();
        for (int e = t; e < 2720; e += 512) {
            int ec  = e / 340;
            int rem = e - ec * 340;
            int rr  = rem / 68;
            int ww  = rem - rr * 68;
            int gh  = h + rr - 2;
            int gw  = ww - 2;
            float v = 0.f;
            if ((unsigned)gh < 64u && (unsigned)gw < 64u)
                v = oth[((size_t)(c0 + ec) * HW + gh) * HW + gw];
            s_oth[ec][rr][ww] = v;
        }
        __syncthreads();

        float cv = c2[((size_t)(c0 + cg) * HW + h) * HW + w];
        x2 = fmaf(cv, cv, x2);
        #pragma unroll
        for (int o = 0; o < 25; ++o)
            acc[o] = fmaf(cv, s_oth[cg][o / 5][w + (o % 5)], acc[o]);
    }

    __syncthreads();
    if (cg >= 4) {
        #pragma unroll
        for (int o = 0; o < 25; ++o) s_acc[o][cg - 4][w] = acc[o];
        s_acc[25][cg - 4][w] = x2;
    }
    __syncthreads();
    if (cg < 4) {
        #pragma unroll
        for (int o = 0; o < 25; ++o) s_acc[o][cg][w] += acc[o];
        s_acc[25][cg][w] += x2;
    }
    __syncthreads();

    if (cg == 0) {
        float X2 = s_acc[25][0][w] + s_acc[25][1][w] + s_acc[25][2][w] + s_acc[25][3][w];
        float inv[25];
        #pragma unroll
        for (int o = 0; o < 25; ++o) {
            float cr = s_acc[o][0][w] + s_acc[o][1][w] + s_acc[o][2][w] + s_acc[o][3][w];
            int gh = h + (o / 5) - 2;
            int gw = w + (o % 5) - 2;
            float y2v = 1e20f;
            if ((unsigned)gh < 64u && (unsigned)gw < 64u)
                y2v = g_y2[(n * HW + gh) * HW + gw];
            float dist = X2 + y2v - 2.f * cr;
            inv[o] = 1.f / (dist + 1e-5f);
        }
        float m = inv[0];
        #pragma unroll
        for (int o = 1; o < 25; ++o) m = fmaxf(m, inv[o]);
        float s = 0.f;
        #pragma unroll
        for (int o = 0; o < 25; ++o) { inv[o] = expf(inv[o] - m); s += inv[o]; }
        float rs = 1.f / s;
        #pragma unroll
        for (int o = 0; o < 25; ++o)
            g_wgt[((o * NPAIR + n) * HW + h) * HW + w] = inv[o] * rs;
    }
}

// ---------------------------------------------------------------------------
__global__ __launch_bounds__(256)
void warp_kernel()
{
    __shared__ float s_w25[25][64];
    __shared__ float s_oth[4][5][68];

    int nb = blockIdx.x;
    int n = nb >> 6, h = nb & 63;
    int t = threadIdx.x;

    for (int e = t; e < 1600; e += 256) {
        int o = e >> 6, ww = e & 63;
        s_w25[o][ww] = g_wgt[((o * NPAIR + n) * HW + h) * HW + ww];
    }

    const float* oth = g_sbuf + (size_t)n       * C1 * HW * HW;
    const float* cim = g_sbuf + (size_t)(2 + n) * C1 * HW * HW;
    int cc = t >> 6, w = t & 63;

    for (int c0 = 0; c0 < C1; c0 += 4) {
        __syncthreads();
        for (int e = t; e < 1360; e += 256) {
            int ec  = e / 340;
            int rem = e - ec * 340;
            int rr  = rem / 68;
            int ww  = rem - rr * 68;
            int gh  = h + rr - 2;
            int gw  = ww - 2;
            float v = 0.f;
            if ((unsigned)gh < 64u && (unsigned)gw < 64u)
                v = oth[((size_t)(c0 + ec) * HW + gh) * HW + gw];
            s_oth[ec][rr][ww] = v;
        }
        __syncthreads();

        float civ = cim[((size_t)(c0 + cc) * HW + h) * HW + w];
        float a = 0.f;
        #pragma unroll
        for (int o = 0; o < 25; ++o)
            a = fmaf(s_w25[o][w], s_oth[cc][o / 5][w + (o % 5)], a);
        float res = 0.5f * (civ + a * (1.0f / 25.0f));
        g_final[(((size_t)n * HW + h) * HW + w) * C1 + c0 + cc] = res;
    }
}

// ---------------------------------------------------------------------------
__global__ void wt_kernel(const float* __restrict__ lw)
{
    int o = blockIdx.x, c = threadIdx.x;
    g_WT[c * NCLS + o] = lw[o * 256 + c];
}

// ---------------------------------------------------------------------------
__global__ __launch_bounds__(128)
void head_kernel(const float* __restrict__ lb, float* __restrict__ xout)
{
    __shared__ float s_x[8][256];
    __shared__ float s_red[128];

    int pg = blockIdx.x;
    int t  = threadIdx.x;

    for (int e = t; e < 2048; e += 128) {
        int pp = e >> 8, c = e & 255;
        s_x[pp][c] = g_final[((size_t)pg * 8 + pp) * 256 + c];
    }
    __syncthreads();

    float acc[8];
    #pragma unroll
    for (int pp = 0; pp < 8; ++pp) acc[pp] = 0.f;

    if (t < NCLS) {
        for (int c = 0; c < 256; ++c) {
            float wv = g_WT[c * NCLS + t];
            #pragma unroll
            for (int pp = 0; pp < 8; ++pp)
                acc[pp] = fmaf(s_x[pp][c], wv, acc[pp]);
        }
        float bias = lb[t];
        #pragma unroll
        for (int pp = 0; pp < 8; ++pp) acc[pp] += bias;
    }

    for (int pp = 0; pp < 8; ++pp) {
        __syncthreads();
        s_red[t] = (t < NCLS) ? acc[pp] : -3.4e38f;
        __syncthreads();
        for (int s = 64; s > 0; s >>= 1) {
            if (t < s) s_red[t] = fmaxf(s_red[t], s_red[t + s]);
            __syncthreads();
        }
        float mx = s_red[0];
        __syncthreads();
        s_red[t] = (t < NCLS) ? expf(acc[pp] - mx) : 0.f;
        __syncthreads();
        for (int s = 64; s > 0; s >>= 1) {
            if (t < s) s_red[t] += s_red[t + s];
            __syncthreads();
        }
        float lse = mx + logf(s_red[0]);

        int pix = pg * 8 + pp;
        int n = pix >> 12, h = (pix >> 6) & 63, w = pix & 63;
        if (t < NCLS)
            xout[(((size_t)n * NCLS + t) * HW + h) * HW + w] = acc[pp] - lse;
    }
}

// ---------------------------------------------------------------------------
extern "C" void kernel_launch(void* const* d_in, const int* in_sizes, int n_in,
                              void* d_out, int out_size)
{
    const float* clip  = (const float*)d_in[0];
    const float* embW  = (const float*)d_in[2];
    const float* eg    = (const float*)d_in[3];
    const float* eb    = (const float*)d_in[4];
    const float* em    = (const float*)d_in[5];
    const float* ev    = (const float*)d_in[6];
    const float* emb2W = (const float*)d_in[7];
    const float* e2g   = (const float*)d_in[8];
    const float* e2b   = (const float*)d_in[9];
    const float* e2m   = (const float*)d_in[10];
    const float* e2v   = (const float*)d_in[11];
    const float* lastW = (const float*)d_in[12];
    const float* lastb = (const float*)d_in[13];

    float* xout = (float*)d_out;
    float* ce2  = (float*)d_out + X_ELEMS;

    cudaFuncSetAttribute(conv_mma<C2, false>,
        cudaFuncAttributeMaxDynamicSharedMemorySize, SMEM_SZ);
    cudaFuncSetAttribute(conv_mma<C1, true>,
        cudaFuncAttributeMaxDynamicSharedMemorySize, SMEM_SZ);

    prep_x<<<NIMG * CIN * HW * HW / 256, 256>>>(clip);
    prep_w<<<C1 * KTOT / 2 / 256, 256>>>(embW,  g_A1hi, g_A1lo);
    prep_w<<<C2 * KTOT / 2 / 256, 256>>>(emb2W, g_A2hi, g_A2lo);

    conv_mma<C2, false><<<dim3(32, 1, NIMG), 512, SMEM_SZ>>>(
        g_A2hi, g_A2lo, e2g, e2b, e2m, e2v, ce2);
    conv_mma<C1, true><<<dim3(32, 2, NIMG), 512, SMEM_SZ>>>(
        g_A1hi, g_A1lo, eg, eb, em, ev, nullptr);

    y2_kernel <<<NPAIR * HW, 64>>>(ce2);
    wgt_kernel<<<NPAIR * HW, 512>>>(ce2);
    warp_kernel<<<NPAIR * HW, 256>>>();
    wt_kernel  <<<NCLS, 256>>>(lastW);
    head_kernel<<<(NPAIR * HW * HW) / 8, 128>>>(lastb, xout);
}

// round 12
// speedup vs baseline: 10.9665x; 10.9665x over previous
#include <cuda_runtime.h>
#include <math.h>

// ---------------------------------------------------------------------------
// WarpNet — Round 12: full Winograd F(2x2,3x3) convs, fp32 FMA pipe.
// ROOT-CAUSE FIX: __device__ scratch symbols are NEVER passed from host code
// (host-passed device symbols resolve to the HOST SHADOW via GB300 ATS,
// silently splitting each array into two coherent copies). All scratch is
// accessed via device-code symbol references only.
// ---------------------------------------------------------------------------

#define NIMG   4
#define CIN    512
#define HW     64
#define C1     256
#define C2     128
#define NCLS   124
#define NPAIR  2
#define NT     4096
#define X_ELEMS (2 * NCLS * HW * HW)

// ---------------- scratch (device globals; device-code access ONLY) ---------
__device__ float g_sbuf [NIMG * C1 * HW * HW];
__device__ float g_y2   [NPAIR * HW * HW];
__device__ float g_wgt  [25 * NPAIR * HW * HW];
__device__ float g_final[NPAIR * HW * HW * C1];
__device__ float g_WT   [256 * NCLS];
__device__ float g_V [16 * CIN * NT];
__device__ float g_U1[16 * CIN * C1];
__device__ float g_U2[16 * CIN * C2];
__device__ float g_M1[16 * C1 * NT];
__device__ float g_M2[16 * C2 * NT];

// device-side symbol selection (never expose symbols to host code)
template<int CO> __device__ __forceinline__ float* Uptr() {
    return (CO == C1) ? g_U1 : g_U2;
}
template<int CO> __device__ __forceinline__ float* Mptr() {
    return (CO == C1) ? g_M1 : g_M2;
}

// ---------------------------------------------------------------------------
// Weight transform U = G g G^T, layout U[xi][ci][co] (coalesced in co)
// ---------------------------------------------------------------------------
template<int CO>
__global__ void prep_u(const float* __restrict__ W)
{
    float* U = Uptr<CO>();
    int ci = blockIdx.x, co = threadIdx.x;
    const float* g = W + ((size_t)co * CIN + ci) * 9;
    float g0[3] = {g[0], g[1], g[2]};
    float g1[3] = {g[3], g[4], g[5]};
    float g2[3] = {g[6], g[7], g[8]};
    float tr[4][3];
    #pragma unroll
    for (int c = 0; c < 3; ++c) {
        tr[0][c] = g0[c];
        tr[1][c] = 0.5f * (g0[c] + g1[c] + g2[c]);
        tr[2][c] = 0.5f * (g0[c] - g1[c] + g2[c]);
        tr[3][c] = g2[c];
    }
    #pragma unroll
    for (int r = 0; r < 4; ++r) {
        float u0 = tr[r][0];
        float u1 = 0.5f * (tr[r][0] + tr[r][1] + tr[r][2]);
        float u2 = 0.5f * (tr[r][0] - tr[r][1] + tr[r][2]);
        float u3 = tr[r][2];
        U[((size_t)(r * 4 + 0) * CIN + ci) * CO + co] = u0;
        U[((size_t)(r * 4 + 1) * CIN + ci) * CO + co] = u1;
        U[((size_t)(r * 4 + 2) * CIN + ci) * CO + co] = u2;
        U[((size_t)(r * 4 + 3) * CIN + ci) * CO + co] = u3;
    }
}

// ---------------------------------------------------------------------------
// Input transform V = B^T d B, layout V[xi][ci][img*1024 + tile]
// ---------------------------------------------------------------------------
__global__ __launch_bounds__(256)
void prep_v(const float* __restrict__ x)
{
    int b = blockIdx.x;               // (img*512 + ci)*4 + quarter
    int q  = b & 3;
    int ic = b >> 2;
    int img = ic >> 9, ci = ic & 511;
    int t = q * 256 + threadIdx.x;    // 0..1023
    int ty = t >> 5, tx = t & 31;
    const float* p = x + ((size_t)img * CIN + ci) * HW * HW;
    int h0 = 2 * ty - 1, w0 = 2 * tx - 1;

    float d[4][4];
    #pragma unroll
    for (int r = 0; r < 4; ++r)
        #pragma unroll
        for (int c = 0; c < 4; ++c) {
            int gh = h0 + r, gw = w0 + c;
            d[r][c] = ((unsigned)gh < 64u && (unsigned)gw < 64u) ? p[gh * 64 + gw] : 0.f;
        }
    float tt[4][4];
    #pragma unroll
    for (int c = 0; c < 4; ++c) {
        tt[0][c] = d[0][c] - d[2][c];
        tt[1][c] = d[1][c] + d[2][c];
        tt[2][c] = d[2][c] - d[1][c];
        tt[3][c] = d[1][c] - d[3][c];
    }
    int base = (img << 10) + t;
    #pragma unroll
    for (int r = 0; r < 4; ++r) {
        float v0 = tt[r][0] - tt[r][2];
        float v1 = tt[r][1] + tt[r][2];
        float v2 = tt[r][2] - tt[r][1];
        float v3 = tt[r][1] - tt[r][3];
        g_V[((size_t)(r * 4 + 0) * CIN + ci) * NT + base] = v0;
        g_V[((size_t)(r * 4 + 1) * CIN + ci) * NT + base] = v1;
        g_V[((size_t)(r * 4 + 2) * CIN + ci) * NT + base] = v2;
        g_V[((size_t)(r * 4 + 3) * CIN + ci) * NT + base] = v3;
    }
}

// ---------------------------------------------------------------------------
// GEMM: M[xi][co][t] = sum_ci U[xi][ci][co] * V[xi][ci][t]
// Block 64co x 256t, K chunks of 8 (validated 90%-of-FFMA-peak structure).
// ---------------------------------------------------------------------------
template<int CO>
__global__ __launch_bounds__(256, 2)
void gemm_wino()
{
    __shared__ float sU[8][64];
    __shared__ float sV[8][256];

    const float* U = Uptr<CO>();
    float*       M = Mptr<CO>();

    const int xi  = blockIdx.z;
    const int co0 = blockIdx.y * 64;
    const int t0  = blockIdx.x * 256;
    const int t   = threadIdx.x;
    const int l   = t & 31;
    const int co8 = (t >> 5) * 8;

    const float* Ub = U + (size_t)xi * CIN * CO;
    const float* Vb = g_V + (size_t)xi * CIN * NT;

    float acc[8][8];
    #pragma unroll
    for (int j = 0; j < 8; ++j)
        #pragma unroll
        for (int i = 0; i < 8; ++i) acc[j][i] = 0.f;

    for (int k0 = 0; k0 < CIN; k0 += 8) {
        __syncthreads();
        {
            int k = t >> 6, c = t & 63;
            sU[k][c]     = Ub[(size_t)(k0 + k) * CO + co0 + c];
            sU[k + 4][c] = Ub[(size_t)(k0 + k + 4) * CO + co0 + c];
        }
        #pragma unroll
        for (int j = 0; j < 8; ++j)
            sV[j][t] = Vb[(size_t)(k0 + j) * NT + t0 + t];
        __syncthreads();

        #pragma unroll
        for (int k = 0; k < 8; ++k) {
            float u[8], v[8];
            #pragma unroll
            for (int j = 0; j < 8; ++j) u[j] = sU[k][co8 + j];    // warp-uniform
            #pragma unroll
            for (int i = 0; i < 8; ++i) v[i] = sV[k][l + 32 * i]; // conflict-free
            #pragma unroll
            for (int j = 0; j < 8; ++j)
                #pragma unroll
                for (int i = 0; i < 8; ++i)
                    acc[j][i] = fmaf(u[j], v[i], acc[j][i]);
        }
    }

    #pragma unroll
    for (int j = 0; j < 8; ++j) {
        float* mb = M + ((size_t)xi * CO + co0 + co8 + j) * NT + t0 + l;
        #pragma unroll
        for (int i = 0; i < 8; ++i) mb[32 * i] = acc[j][i];
    }
}

// ---------------------------------------------------------------------------
// Output transform Y = A^T M A, then BN + ReLU -> NCHW
// ---------------------------------------------------------------------------
template<int CO, bool TO_SBUF>
__global__ void out_wino(const float* __restrict__ bg, const float* __restrict__ bb,
                         const float* __restrict__ bm, const float* __restrict__ bv,
                         float* __restrict__ out_ext)
{
    const float* M = Mptr<CO>();
    int co = blockIdx.y;
    int tg = blockIdx.x * 256 + threadIdx.x;

    float m[16];
    #pragma unroll
    for (int xi = 0; xi < 16; ++xi)
        m[xi] = M[((size_t)xi * CO + co) * NT + tg];

    float a0[4], a1[4];
    #pragma unroll
    for (int c = 0; c < 4; ++c) {
        a0[c] = m[c] + m[4 + c] + m[8 + c];
        a1[c] = m[4 + c] - m[8 + c] - m[12 + c];
    }
    float y00 = a0[0] + a0[1] + a0[2];
    float y01 = a0[1] - a0[2] - a0[3];
    float y10 = a1[0] + a1[1] + a1[2];
    float y11 = a1[1] - a1[2] - a1[3];

    float sc = bg[co] * rsqrtf(bv[co] + 1e-5f);
    float bi = bb[co] - bm[co] * sc;
    y00 = fmaf(y00, sc, bi); y01 = fmaf(y01, sc, bi);
    y10 = fmaf(y10, sc, bi); y11 = fmaf(y11, sc, bi);
    y00 = y00 > 0.f ? y00 : 0.f;  y01 = y01 > 0.f ? y01 : 0.f;
    y10 = y10 > 0.f ? y10 : 0.f;  y11 = y11 > 0.f ? y11 : 0.f;

    int img = tg >> 10, tile = tg & 1023;
    int ty = tile >> 5, tx = tile & 31;
    float* op = TO_SBUF ? g_sbuf : out_ext;
    float* ob = op + (((size_t)img * CO + co) * HW + 2 * ty) * HW + 2 * tx;
    *(float2*)ob        = make_float2(y00, y01);
    *(float2*)(ob + 64) = make_float2(y10, y11);
}

// ---------------------------------------------------------------------------
// Tail (validated): y2 / wgt read ce2 via harness pointer; rest device-direct.
// ---------------------------------------------------------------------------
__global__ void y2_kernel(const float* __restrict__ ce2)
{
    int nb = blockIdx.x;
    int n = nb >> 6, h = nb & 63, w = threadIdx.x;
    const float* p = ce2 + ((size_t)n * C2 * HW + h) * HW + w;
    float acc = 0.f;
    for (int c = 0; c < C2; ++c) {
        float v = p[(size_t)c * HW * HW];
        acc = fmaf(v, v, acc);
    }
    g_y2[(n * HW + h) * HW + w] = acc;
}

__global__ __launch_bounds__(512)
void wgt_kernel(const float* __restrict__ ce2)
{
    __shared__ float s_oth[8][5][68];
    __shared__ float s_acc[26][4][64];

    int nb = blockIdx.x;
    int n = nb >> 6, h = nb & 63;
    int t = threadIdx.x;
    int cg = t >> 6, w = t & 63;

    float acc[25];
    #pragma unroll
    for (int o = 0; o < 25; ++o) acc[o] = 0.f;
    float x2 = 0.f;

    const float* oth = ce2 + (size_t)n       * C2 * HW * HW;
    const float* c2  = ce2 + (size_t)(2 + n) * C2 * HW * HW;

    for (int c0 = 0; c0 < C2; c0 += 8) {
        __syncthreads();
        for (int e = t; e < 2720; e += 512) {
            int ec  = e / 340;
            int rem = e - ec * 340;
            int rr  = rem / 68;
            int ww  = rem - rr * 68;
            int gh  = h + rr - 2;
            int gw  = ww - 2;
            float v = 0.f;
            if ((unsigned)gh < 64u && (unsigned)gw < 64u)
                v = oth[((size_t)(c0 + ec) * HW + gh) * HW + gw];
            s_oth[ec][rr][ww] = v;
        }
        __syncthreads();

        float cv = c2[((size_t)(c0 + cg) * HW + h) * HW + w];
        x2 = fmaf(cv, cv, x2);
        #pragma unroll
        for (int o = 0; o < 25; ++o)
            acc[o] = fmaf(cv, s_oth[cg][o / 5][w + (o % 5)], acc[o]);
    }

    __syncthreads();
    if (cg >= 4) {
        #pragma unroll
        for (int o = 0; o < 25; ++o) s_acc[o][cg - 4][w] = acc[o];
        s_acc[25][cg - 4][w] = x2;
    }
    __syncthreads();
    if (cg < 4) {
        #pragma unroll
        for (int o = 0; o < 25; ++o) s_acc[o][cg][w] += acc[o];
        s_acc[25][cg][w] += x2;
    }
    __syncthreads();

    if (cg == 0) {
        float X2 = s_acc[25][0][w] + s_acc[25][1][w] + s_acc[25][2][w] + s_acc[25][3][w];
        float inv[25];
        #pragma unroll
        for (int o = 0; o < 25; ++o) {
            float cr = s_acc[o][0][w] + s_acc[o][1][w] + s_acc[o][2][w] + s_acc[o][3][w];
            int gh = h + (o / 5) - 2;
            int gw = w + (o % 5) - 2;
            float y2v = 1e20f;
            if ((unsigned)gh < 64u && (unsigned)gw < 64u)
                y2v = g_y2[(n * HW + gh) * HW + gw];
            float dist = X2 + y2v - 2.f * cr;
            inv[o] = 1.f / (dist + 1e-5f);
        }
        float m = inv[0];
        #pragma unroll
        for (int o = 1; o < 25; ++o) m = fmaxf(m, inv[o]);
        float s = 0.f;
        #pragma unroll
        for (int o = 0; o < 25; ++o) { inv[o] = expf(inv[o] - m); s += inv[o]; }
        float rs = 1.f / s;
        #pragma unroll
        for (int o = 0; o < 25; ++o)
            g_wgt[((o * NPAIR + n) * HW + h) * HW + w] = inv[o] * rs;
    }
}

__global__ __launch_bounds__(256)
void warp_kernel()
{
    __shared__ float s_w25[25][64];
    __shared__ float s_oth[4][5][68];

    int nb = blockIdx.x;
    int n = nb >> 6, h = nb & 63;
    int t = threadIdx.x;

    for (int e = t; e < 1600; e += 256) {
        int o = e >> 6, ww = e & 63;
        s_w25[o][ww] = g_wgt[((o * NPAIR + n) * HW + h) * HW + ww];
    }

    const float* oth = g_sbuf + (size_t)n       * C1 * HW * HW;
    const float* cim = g_sbuf + (size_t)(2 + n) * C1 * HW * HW;
    int cc = t >> 6, w = t & 63;

    for (int c0 = 0; c0 < C1; c0 += 4) {
        __syncthreads();
        for (int e = t; e < 1360; e += 256) {
            int ec  = e / 340;
            int rem = e - ec * 340;
            int rr  = rem / 68;
            int ww  = rem - rr * 68;
            int gh  = h + rr - 2;
            int gw  = ww - 2;
            float v = 0.f;
            if ((unsigned)gh < 64u && (unsigned)gw < 64u)
                v = oth[((size_t)(c0 + ec) * HW + gh) * HW + gw];
            s_oth[ec][rr][ww] = v;
        }
        __syncthreads();

        float civ = cim[((size_t)(c0 + cc) * HW + h) * HW + w];
        float a = 0.f;
        #pragma unroll
        for (int o = 0; o < 25; ++o)
            a = fmaf(s_w25[o][w], s_oth[cc][o / 5][w + (o % 5)], a);
        float res = 0.5f * (civ + a * (1.0f / 25.0f));
        g_final[(((size_t)n * HW + h) * HW + w) * C1 + c0 + cc] = res;
    }
}

__global__ void wt_kernel(const float* __restrict__ lw)
{
    int o = blockIdx.x, c = threadIdx.x;
    g_WT[c * NCLS + o] = lw[o * 256 + c];
}

__global__ __launch_bounds__(128)
void head_kernel(const float* __restrict__ lb, float* __restrict__ xout)
{
    __shared__ float s_x[8][256];
    __shared__ float s_red[128];

    int pg = blockIdx.x;
    int t  = threadIdx.x;

    for (int e = t; e < 2048; e += 128) {
        int pp = e >> 8, c = e & 255;
        s_x[pp][c] = g_final[((size_t)pg * 8 + pp) * 256 + c];
    }
    __syncthreads();

    float acc[8];
    #pragma unroll
    for (int pp = 0; pp < 8; ++pp) acc[pp] = 0.f;

    if (t < NCLS) {
        for (int c = 0; c < 256; ++c) {
            float wv = g_WT[c * NCLS + t];
            #pragma unroll
            for (int pp = 0; pp < 8; ++pp)
                acc[pp] = fmaf(s_x[pp][c], wv, acc[pp]);
        }
        float bias = lb[t];
        #pragma unroll
        for (int pp = 0; pp < 8; ++pp) acc[pp] += bias;
    }

    for (int pp = 0; pp < 8; ++pp) {
        __syncthreads();
        s_red[t] = (t < NCLS) ? acc[pp] : -3.4e38f;
        __syncthreads();
        for (int s = 64; s > 0; s >>= 1) {
            if (t < s) s_red[t] = fmaxf(s_red[t], s_red[t + s]);
            __syncthreads();
        }
        float mx = s_red[0];
        __syncthreads();
        s_red[t] = (t < NCLS) ? expf(acc[pp] - mx) : 0.f;
        __syncthreads();
        for (int s = 64; s > 0; s >>= 1) {
            if (t < s) s_red[t] += s_red[t + s];
            __syncthreads();
        }
        float lse = mx + logf(s_red[0]);

        int pix = pg * 8 + pp;
        int n = pix >> 12, h = (pix >> 6) & 63, w = pix & 63;
        if (t < NCLS)
            xout[(((size_t)n * NCLS + t) * HW + h) * HW + w] = acc[pp] - lse;
    }
}

// ---------------------------------------------------------------------------
extern "C" void kernel_launch(void* const* d_in, const int* in_sizes, int n_in,
                              void* d_out, int out_size)
{
    const float* clip  = (const float*)d_in[0];
    const float* embW  = (const float*)d_in[2];
    const float* eg    = (const float*)d_in[3];
    const float* eb    = (const float*)d_in[4];
    const float* em    = (const float*)d_in[5];
    const float* ev    = (const float*)d_in[6];
    const float* emb2W = (const float*)d_in[7];
    const float* e2g   = (const float*)d_in[8];
    const float* e2b   = (const float*)d_in[9];
    const float* e2m   = (const float*)d_in[10];
    const float* e2v   = (const float*)d_in[11];
    const float* lastW = (const float*)d_in[12];
    const float* lastb = (const float*)d_in[13];

    float* xout = (float*)d_out;
    float* ce2  = (float*)d_out + X_ELEMS;   // clip_emb2 output region

    // Winograd transforms (scratch accessed device-side only)
    prep_u<C1><<<CIN, C1>>>(embW);
    prep_u<C2><<<CIN, C2>>>(emb2W);
    prep_v<<<NIMG * CIN * 4, 256>>>(clip);

    // 16 GEMMs per conv
    gemm_wino<C2><<<dim3(NT / 256, C2 / 64, 16), 256>>>();
    gemm_wino<C1><<<dim3(NT / 256, C1 / 64, 16), 256>>>();

    // inverse transform + BN + ReLU
    out_wino<C2, false><<<dim3(NT / 256, C2), 256>>>(e2g, e2b, e2m, e2v, ce2);
    out_wino<C1, true ><<<dim3(NT / 256, C1), 256>>>(eg, eb, em, ev, nullptr);

    // tail
    y2_kernel <<<NPAIR * HW, 64>>>(ce2);
    wgt_kernel<<<NPAIR * HW, 512>>>(ce2);
    warp_kernel<<<NPAIR * HW, 256>>>();
    wt_kernel  <<<NCLS, 256>>>(lastW);
    head_kernel<<<(NPAIR * HW * HW) / 8, 128>>>(lastb, xout);
}

// round 13
// speedup vs baseline: 11.3588x; 1.0358x over previous
#include <cuda_runtime.h>
#include <math.h>

// ---------------------------------------------------------------------------
// WarpNet — Round 13: Winograd F(2x2,3x3), GEMM inner loop vectorized.
//   Thread tile remapped from stride-32 scalars to two float4 groups
//   (t = 4l and 128+4l): 4x LDS.128 + 64 FMA per k-step (was 16 scalar LDS).
//   All scratch accessed via device-code symbols ONLY (GB300 ATS pitfall).
// ---------------------------------------------------------------------------

#define NIMG   4
#define CIN    512
#define HW     64
#define C1     256
#define C2     128
#define NCLS   124
#define NPAIR  2
#define NT     4096
#define X_ELEMS (2 * NCLS * HW * HW)

// ---------------- scratch (device globals; device-code access ONLY) ---------
__device__ float g_sbuf [NIMG * C1 * HW * HW];
__device__ float g_y2   [NPAIR * HW * HW];
__device__ float g_wgt  [25 * NPAIR * HW * HW];
__device__ float g_final[NPAIR * HW * HW * C1];
__device__ float g_WT   [256 * NCLS];
__device__ float g_V [16 * CIN * NT];
__device__ float g_U1[16 * CIN * C1];
__device__ float g_U2[16 * CIN * C2];
__device__ float g_M1[16 * C1 * NT];
__device__ float g_M2[16 * C2 * NT];

template<int CO> __device__ __forceinline__ float* Uptr() {
    return (CO == C1) ? g_U1 : g_U2;
}
template<int CO> __device__ __forceinline__ float* Mptr() {
    return (CO == C1) ? g_M1 : g_M2;
}

// ---------------------------------------------------------------------------
// Weight transform U = G g G^T, layout U[xi][ci][co]
// ---------------------------------------------------------------------------
template<int CO>
__global__ void prep_u(const float* __restrict__ W)
{
    float* U = Uptr<CO>();
    int ci = blockIdx.x, co = threadIdx.x;
    const float* g = W + ((size_t)co * CIN + ci) * 9;
    float g0[3] = {g[0], g[1], g[2]};
    float g1[3] = {g[3], g[4], g[5]};
    float g2[3] = {g[6], g[7], g[8]};
    float tr[4][3];
    #pragma unroll
    for (int c = 0; c < 3; ++c) {
        tr[0][c] = g0[c];
        tr[1][c] = 0.5f * (g0[c] + g1[c] + g2[c]);
        tr[2][c] = 0.5f * (g0[c] - g1[c] + g2[c]);
        tr[3][c] = g2[c];
    }
    #pragma unroll
    for (int r = 0; r < 4; ++r) {
        float u0 = tr[r][0];
        float u1 = 0.5f * (tr[r][0] + tr[r][1] + tr[r][2]);
        float u2 = 0.5f * (tr[r][0] - tr[r][1] + tr[r][2]);
        float u3 = tr[r][2];
        U[((size_t)(r * 4 + 0) * CIN + ci) * CO + co] = u0;
        U[((size_t)(r * 4 + 1) * CIN + ci) * CO + co] = u1;
        U[((size_t)(r * 4 + 2) * CIN + ci) * CO + co] = u2;
        U[((size_t)(r * 4 + 3) * CIN + ci) * CO + co] = u3;
    }
}

// ---------------------------------------------------------------------------
// Input transform V = B^T d B, layout V[xi][ci][img*1024 + tile]
// ---------------------------------------------------------------------------
__global__ __launch_bounds__(256)
void prep_v(const float* __restrict__ x)
{
    int b = blockIdx.x;
    int q  = b & 3;
    int ic = b >> 2;
    int img = ic >> 9, ci = ic & 511;
    int t = q * 256 + threadIdx.x;
    int ty = t >> 5, tx = t & 31;
    const float* p = x + ((size_t)img * CIN + ci) * HW * HW;
    int h0 = 2 * ty - 1, w0 = 2 * tx - 1;

    float d[4][4];
    #pragma unroll
    for (int r = 0; r < 4; ++r)
        #pragma unroll
        for (int c = 0; c < 4; ++c) {
            int gh = h0 + r, gw = w0 + c;
            d[r][c] = ((unsigned)gh < 64u && (unsigned)gw < 64u) ? p[gh * 64 + gw] : 0.f;
        }
    float tt[4][4];
    #pragma unroll
    for (int c = 0; c < 4; ++c) {
        tt[0][c] = d[0][c] - d[2][c];
        tt[1][c] = d[1][c] + d[2][c];
        tt[2][c] = d[2][c] - d[1][c];
        tt[3][c] = d[1][c] - d[3][c];
    }
    int base = (img << 10) + t;
    #pragma unroll
    for (int r = 0; r < 4; ++r) {
        float v0 = tt[r][0] - tt[r][2];
        float v1 = tt[r][1] + tt[r][2];
        float v2 = tt[r][2] - tt[r][1];
        float v3 = tt[r][1] - tt[r][3];
        g_V[((size_t)(r * 4 + 0) * CIN + ci) * NT + base] = v0;
        g_V[((size_t)(r * 4 + 1) * CIN + ci) * NT + base] = v1;
        g_V[((size_t)(r * 4 + 2) * CIN + ci) * NT + base] = v2;
        g_V[((size_t)(r * 4 + 3) * CIN + ci) * NT + base] = v3;
    }
}

// ---------------------------------------------------------------------------
// GEMM: M[xi][co][t] = sum_ci U[xi][ci][co] * V[xi][ci][t]
// Block 64co x 256t, K chunks of 8. Thread = 8co x {4l..4l+3, 128+4l..+3}.
// All smem traffic via LDS.128 (u: warp-uniform broadcast; v: conflict-free).
// ---------------------------------------------------------------------------
template<int CO>
__global__ __launch_bounds__(256, 2)
void gemm_wino()
{
    __shared__ float sU[8][64];
    __shared__ float sV[8][256];

    const float* U = Uptr<CO>();
    float*       M = Mptr<CO>();

    const int xi  = blockIdx.z;
    const int co0 = blockIdx.y * 64;
    const int t0  = blockIdx.x * 256;
    const int t   = threadIdx.x;
    const int l   = t & 31;
    const int co8 = (t >> 5) * 8;

    const float* Ub = U + (size_t)xi * CIN * CO;
    const float* Vb = g_V + (size_t)xi * CIN * NT;

    float acc[8][8];
    #pragma unroll
    for (int j = 0; j < 8; ++j)
        #pragma unroll
        for (int i = 0; i < 8; ++i) acc[j][i] = 0.f;

    for (int k0 = 0; k0 < CIN; k0 += 8) {
        __syncthreads();
        {
            int k = t >> 6, c = t & 63;
            sU[k][c]     = Ub[(size_t)(k0 + k) * CO + co0 + c];
            sU[k + 4][c] = Ub[(size_t)(k0 + k + 4) * CO + co0 + c];
        }
        #pragma unroll
        for (int j = 0; j < 8; ++j)
            sV[j][t] = Vb[(size_t)(k0 + j) * NT + t0 + t];
        __syncthreads();

        #pragma unroll
        for (int k = 0; k < 8; ++k) {
            float4 u4a = *(const float4*)&sU[k][co8];
            float4 u4b = *(const float4*)&sU[k][co8 + 4];
            float4 va  = *(const float4*)&sV[k][4 * l];
            float4 vb  = *(const float4*)&sV[k][128 + 4 * l];
            float u[8] = {u4a.x, u4a.y, u4a.z, u4a.w, u4b.x, u4b.y, u4b.z, u4b.w};
            float v[8] = {va.x, va.y, va.z, va.w, vb.x, vb.y, vb.z, vb.w};
            #pragma unroll
            for (int j = 0; j < 8; ++j)
                #pragma unroll
                for (int i = 0; i < 8; ++i)
                    acc[j][i] = fmaf(u[j], v[i], acc[j][i]);
        }
    }

    #pragma unroll
    for (int j = 0; j < 8; ++j) {
        float* mb = M + ((size_t)xi * CO + co0 + co8 + j) * NT + t0;
        *(float4*)(mb + 4 * l)       = make_float4(acc[j][0], acc[j][1], acc[j][2], acc[j][3]);
        *(float4*)(mb + 128 + 4 * l) = make_float4(acc[j][4], acc[j][5], acc[j][6], acc[j][7]);
    }
}

// ---------------------------------------------------------------------------
// Output transform Y = A^T M A + BN + ReLU -> NCHW
// ---------------------------------------------------------------------------
template<int CO, bool TO_SBUF>
__global__ void out_wino(const float* __restrict__ bg, const float* __restrict__ bb,
                         const float* __restrict__ bm, const float* __restrict__ bv,
                         float* __restrict__ out_ext)
{
    const float* M = Mptr<CO>();
    int co = blockIdx.y;
    int tg = blockIdx.x * 256 + threadIdx.x;

    float m[16];
    #pragma unroll
    for (int xi = 0; xi < 16; ++xi)
        m[xi] = M[((size_t)xi * CO + co) * NT + tg];

    float a0[4], a1[4];
    #pragma unroll
    for (int c = 0; c < 4; ++c) {
        a0[c] = m[c] + m[4 + c] + m[8 + c];
        a1[c] = m[4 + c] - m[8 + c] - m[12 + c];
    }
    float y00 = a0[0] + a0[1] + a0[2];
    float y01 = a0[1] - a0[2] - a0[3];
    float y10 = a1[0] + a1[1] + a1[2];
    float y11 = a1[1] - a1[2] - a1[3];

    float sc = bg[co] * rsqrtf(bv[co] + 1e-5f);
    float bi = bb[co] - bm[co] * sc;
    y00 = fmaf(y00, sc, bi); y01 = fmaf(y01, sc, bi);
    y10 = fmaf(y10, sc, bi); y11 = fmaf(y11, sc, bi);
    y00 = y00 > 0.f ? y00 : 0.f;  y01 = y01 > 0.f ? y01 : 0.f;
    y10 = y10 > 0.f ? y10 : 0.f;  y11 = y11 > 0.f ? y11 : 0.f;

    int img = tg >> 10, tile = tg & 1023;
    int ty = tile >> 5, tx = tile & 31;
    float* op = TO_SBUF ? g_sbuf : out_ext;
    float* ob = op + (((size_t)img * CO + co) * HW + 2 * ty) * HW + 2 * tx;
    *(float2*)ob        = make_float2(y00, y01);
    *(float2*)(ob + 64) = make_float2(y10, y11);
}

// ---------------------------------------------------------------------------
__global__ void y2_kernel(const float* __restrict__ ce2)
{
    int nb = blockIdx.x;
    int n = nb >> 6, h = nb & 63, w = threadIdx.x;
    const float* p = ce2 + ((size_t)n * C2 * HW + h) * HW + w;
    float acc = 0.f;
    for (int c = 0; c < C2; ++c) {
        float v = p[(size_t)c * HW * HW];
        acc = fmaf(v, v, acc);
    }
    g_y2[(n * HW + h) * HW + w] = acc;
}

__global__ __launch_bounds__(512)
void wgt_kernel(const float* __restrict__ ce2)
{
    __shared__ float s_oth[8][5][68];
    __shared__ float s_acc[26][4][64];

    int nb = blockIdx.x;
    int n = nb >> 6, h = nb & 63;
    int t = threadIdx.x;
    int cg = t >> 6, w = t & 63;

    float acc[25];
    #pragma unroll
    for (int o = 0; o < 25; ++o) acc[o] = 0.f;
    float x2 = 0.f;

    const float* oth = ce2 + (size_t)n       * C2 * HW * HW;
    const float* c2  = ce2 + (size_t)(2 + n) * C2 * HW * HW;

    for (int c0 = 0; c0 < C2; c0 += 8) {
        __syncthreads();
        for (int e = t; e < 2720; e += 512) {
            int ec  = e / 340;
            int rem = e - ec * 340;
            int rr  = rem / 68;
            int ww  = rem - rr * 68;
            int gh  = h + rr - 2;
            int gw  = ww - 2;
            float v = 0.f;
            if ((unsigned)gh < 64u && (unsigned)gw < 64u)
                v = oth[((size_t)(c0 + ec) * HW + gh) * HW + gw];
            s_oth[ec][rr][ww] = v;
        }
        __syncthreads();

        float cv = c2[((size_t)(c0 + cg) * HW + h) * HW + w];
        x2 = fmaf(cv, cv, x2);
        #pragma unroll
        for (int o = 0; o < 25; ++o)
            acc[o] = fmaf(cv, s_oth[cg][o / 5][w + (o % 5)], acc[o]);
    }

    __syncthreads();
    if (cg >= 4) {
        #pragma unroll
        for (int o = 0; o < 25; ++o) s_acc[o][cg - 4][w] = acc[o];
        s_acc[25][cg - 4][w] = x2;
    }
    __syncthreads();
    if (cg < 4) {
        #pragma unroll
        for (int o = 0; o < 25; ++o) s_acc[o][cg][w] += acc[o];
        s_acc[25][cg][w] += x2;
    }
    __syncthreads();

    if (cg == 0) {
        float X2 = s_acc[25][0][w] + s_acc[25][1][w] + s_acc[25][2][w] + s_acc[25][3][w];
        float inv[25];
        #pragma unroll
        for (int o = 0; o < 25; ++o) {
            float cr = s_acc[o][0][w] + s_acc[o][1][w] + s_acc[o][2][w] + s_acc[o][3][w];
            int gh = h + (o / 5) - 2;
            int gw = w + (o % 5) - 2;
            float y2v = 1e20f;
            if ((unsigned)gh < 64u && (unsigned)gw < 64u)
                y2v = g_y2[(n * HW + gh) * HW + gw];
            float dist = X2 + y2v - 2.f * cr;
            inv[o] = 1.f / (dist + 1e-5f);
        }
        float m = inv[0];
        #pragma unroll
        for (int o = 1; o < 25; ++o) m = fmaxf(m, inv[o]);
        float s = 0.f;
        #pragma unroll
        for (int o = 0; o < 25; ++o) { inv[o] = expf(inv[o] - m); s += inv[o]; }
        float rs = 1.f / s;
        #pragma unroll
        for (int o = 0; o < 25; ++o)
            g_wgt[((o * NPAIR + n) * HW + h) * HW + w] = inv[o] * rs;
    }
}

__global__ __launch_bounds__(256)
void warp_kernel()
{
    __shared__ float s_w25[25][64];
    __shared__ float s_oth[4][5][68];

    int nb = blockIdx.x;
    int n = nb >> 6, h = nb & 63;
    int t = threadIdx.x;

    for (int e = t; e < 1600; e += 256) {
        int o = e >> 6, ww = e & 63;
        s_w25[o][ww] = g_wgt[((o * NPAIR + n) * HW + h) * HW + ww];
    }

    const float* oth = g_sbuf + (size_t)n       * C1 * HW * HW;
    const float* cim = g_sbuf + (size_t)(2 + n) * C1 * HW * HW;
    int cc = t >> 6, w = t & 63;

    for (int c0 = 0; c0 < C1; c0 += 4) {
        __syncthreads();
        for (int e = t; e < 1360; e += 256) {
            int ec  = e / 340;
            int rem = e - ec * 340;
            int rr  = rem / 68;
            int ww  = rem - rr * 68;
            int gh  = h + rr - 2;
            int gw  = ww - 2;
            float v = 0.f;
            if ((unsigned)gh < 64u && (unsigned)gw < 64u)
                v = oth[((size_t)(c0 + ec) * HW + gh) * HW + gw];
            s_oth[ec][rr][ww] = v;
        }
        __syncthreads();

        float civ = cim[((size_t)(c0 + cc) * HW + h) * HW + w];
        float a = 0.f;
        #pragma unroll
        for (int o = 0; o < 25; ++o)
            a = fmaf(s_w25[o][w], s_oth[cc][o / 5][w + (o % 5)], a);
        float res = 0.5f * (civ + a * (1.0f / 25.0f));
        g_final[(((size_t)n * HW + h) * HW + w) * C1 + c0 + cc] = res;
    }
}

__global__ void wt_kernel(const float* __restrict__ lw)
{
    int o = blockIdx.x, c = threadIdx.x;
    g_WT[c * NCLS + o] = lw[o * 256 + c];
}

__global__ __launch_bounds__(128)
void head_kernel(const float* __restrict__ lb, float* __restrict__ xout)
{
    __shared__ float s_x[8][256];
    __shared__ float s_red[128];

    int pg = blockIdx.x;
    int t  = threadIdx.x;

    for (int e = t; e < 2048; e += 128) {
        int pp = e >> 8, c = e & 255;
        s_x[pp][c] = g_final[((size_t)pg * 8 + pp) * 256 + c];
    }
    __syncthreads();

    float acc[8];
    #pragma unroll
    for (int pp = 0; pp < 8; ++pp) acc[pp] = 0.f;

    if (t < NCLS) {
        for (int c = 0; c < 256; ++c) {
            float wv = g_WT[c * NCLS + t];
            #pragma unroll
            for (int pp = 0; pp < 8; ++pp)
                acc[pp] = fmaf(s_x[pp][c], wv, acc[pp]);
        }
        float bias = lb[t];
        #pragma unroll
        for (int pp = 0; pp < 8; ++pp) acc[pp] += bias;
    }

    for (int pp = 0; pp < 8; ++pp) {
        __syncthreads();
        s_red[t] = (t < NCLS) ? acc[pp] : -3.4e38f;
        __syncthreads();
        for (int s = 64; s > 0; s >>= 1) {
            if (t < s) s_red[t] = fmaxf(s_red[t], s_red[t + s]);
            __syncthreads();
        }
        float mx = s_red[0];
        __syncthreads();
        s_red[t] = (t < NCLS) ? expf(acc[pp] - mx) : 0.f;
        __syncthreads();
        for (int s = 64; s > 0; s >>= 1) {
            if (t < s) s_red[t] += s_red[t + s];
            __syncthreads();
        }
        float lse = mx + logf(s_red[0]);

        int pix = pg * 8 + pp;
        int n = pix >> 12, h = (pix >> 6) & 63, w = pix & 63;
        if (t < NCLS)
            xout[(((size_t)n * NCLS + t) * HW + h) * HW + w] = acc[pp] - lse;
    }
}

// ---------------------------------------------------------------------------
extern "C" void kernel_launch(void* const* d_in, const int* in_sizes, int n_in,
                              void* d_out, int out_size)
{
    const float* clip  = (const float*)d_in[0];
    const float* embW  = (const float*)d_in[2];
    const float* eg    = (const float*)d_in[3];
    const float* eb    = (const float*)d_in[4];
    const float* em    = (const float*)d_in[5];
    const float* ev    = (const float*)d_in[6];
    const float* emb2W = (const float*)d_in[7];
    const float* e2g   = (const float*)d_in[8];
    const float* e2b   = (const float*)d_in[9];
    const float* e2m   = (const float*)d_in[10];
    const float* e2v   = (const float*)d_in[11];
    const float* lastW = (const float*)d_in[12];
    const float* lastb = (const float*)d_in[13];

    float* xout = (float*)d_out;
    float* ce2  = (float*)d_out + X_ELEMS;

    prep_u<C1><<<CIN, C1>>>(embW);
    prep_u<C2><<<CIN, C2>>>(emb2W);
    prep_v<<<NIMG * CIN * 4, 256>>>(clip);

    gemm_wino<C2><<<dim3(NT / 256, C2 / 64, 16), 256>>>();
    gemm_wino<C1><<<dim3(NT / 256, C1 / 64, 16), 256>>>();

    out_wino<C2, false><<<dim3(NT / 256, C2), 256>>>(e2g, e2b, e2m, e2v, ce2);
    out_wino<C1, true ><<<dim3(NT / 256, C1), 256>>>(eg, eb, em, ev, nullptr);

    y2_kernel <<<NPAIR * HW, 64>>>(ce2);
    wgt_kernel<<<NPAIR * HW, 512>>>(ce2);
    warp_kernel<<<NPAIR * HW, 256>>>();
    wt_kernel  <<<NCLS, 256>>>(lastW);
    head_kernel<<<(NPAIR * HW * HW) / 8, 128>>>(lastb, xout);
}

// round 14
// speedup vs baseline: 17.0634x; 1.5022x over previous
#include <cuda_runtime.h>
#include <math.h>

// ---------------------------------------------------------------------------
// WarpNet — Round 14: Winograd F(4x4,3x3) convolutions (fp32 FMA pipe).
//   36 GEMMs of CO x 512 x 1024 (was 16 of CO x 512 x 4096): 12.9G -> 7.25G MACs.
//   All scratch via device-code symbols ONLY (GB300 ATS host-shadow pitfall).
// ---------------------------------------------------------------------------

#define NIMG   4
#define CIN    512
#define HW     64
#define C1     256
#define C2     128
#define NCLS   124
#define NPAIR  2
#define NT2    1024            // 4 img x 256 tiles (4x4 output per tile)
#define X_ELEMS (2 * NCLS * HW * HW)

// ---------------- scratch (device globals; device-code access ONLY) ---------
__device__ float g_sbuf [NIMG * C1 * HW * HW];
__device__ float g_y2   [NPAIR * HW * HW];
__device__ float g_wgt  [25 * NPAIR * HW * HW];
__device__ float g_final[NPAIR * HW * HW * C1];
__device__ float g_WT   [256 * NCLS];
__device__ float g_V [36 * CIN * NT2];
__device__ float g_U1[36 * CIN * C1];
__device__ float g_U2[36 * CIN * C2];
__device__ float g_M1[36 * C1 * NT2];
__device__ float g_M2[36 * C2 * NT2];

template<int CO> __device__ __forceinline__ float* Uptr() {
    return (CO == C1) ? g_U1 : g_U2;
}
template<int CO> __device__ __forceinline__ float* Mptr() {
    return (CO == C1) ? g_M1 : g_M2;
}

// ---------------------------------------------------------------------------
// Weight transform U = G g G^T (6x6), layout U[xi][ci][co]
// G rows: [1/4,0,0], [-1/6,-1/6,-1/6], [-1/6,1/6,-1/6],
//         [1/24,1/12,1/6], [1/24,-1/12,1/6], [0,0,1]
// ---------------------------------------------------------------------------
__device__ __forceinline__ void gxform(const float a, const float b, const float c,
                                       float* o)
{
    o[0] = 0.25f * a;
    o[1] = -(a + b + c) * (1.f / 6.f);
    o[2] = -(a - b + c) * (1.f / 6.f);
    o[3] = a * (1.f / 24.f) + b * (1.f / 12.f) + c * (1.f / 6.f);
    o[4] = a * (1.f / 24.f) - b * (1.f / 12.f) + c * (1.f / 6.f);
    o[5] = c;
}

template<int CO>
__global__ void prep_u(const float* __restrict__ W)
{
    float* U = Uptr<CO>();
    int ci = blockIdx.x, co = threadIdx.x;
    const float* g = W + ((size_t)co * CIN + ci) * 9;
    float t6[6][3];
    #pragma unroll
    for (int c = 0; c < 3; ++c) {
        float col[6];
        gxform(g[c], g[3 + c], g[6 + c], col);
        #pragma unroll
        for (int r = 0; r < 6; ++r) t6[r][c] = col[r];
    }
    #pragma unroll
    for (int r = 0; r < 6; ++r) {
        float u[6];
        gxform(t6[r][0], t6[r][1], t6[r][2], u);
        #pragma unroll
        for (int s = 0; s < 6; ++s)
            U[((size_t)(r * 6 + s) * CIN + ci) * CO + co] = u[s];
    }
}

// ---------------------------------------------------------------------------
// Input transform V = B^T d B (6x6), layout V[xi][ci][img*256 + tile]
// B^T rows: [4,0,-5,0,1,0],[0,-4,-4,1,1,0],[0,4,-4,-1,1,0],
//           [0,-2,-1,2,1,0],[0,2,-1,-2,1,0],[0,4,0,-5,0,1]
// ---------------------------------------------------------------------------
__device__ __forceinline__ void btform(const float* d, float* o)
{
    o[0] = 4.f * d[0] - 5.f * d[2] + d[4];
    o[1] = -4.f * d[1] - 4.f * d[2] + d[3] + d[4];
    o[2] =  4.f * d[1] - 4.f * d[2] - d[3] + d[4];
    o[3] = -2.f * d[1] - d[2] + 2.f * d[3] + d[4];
    o[4] =  2.f * d[1] - d[2] - 2.f * d[3] + d[4];
    o[5] =  4.f * d[1] - 5.f * d[3] + d[5];
}

__global__ __launch_bounds__(256)
void prep_v(const float* __restrict__ x)
{
    int b = blockIdx.x;                  // img*512 + ci
    int img = b >> 9, ci = b & 511;
    int t = threadIdx.x;                 // tile 0..255
    int ty = t >> 4, tx = t & 15;
    const float* p = x + ((size_t)img * CIN + ci) * HW * HW;
    int h0 = 4 * ty - 1, w0 = 4 * tx - 1;

    float d[6][6];
    #pragma unroll
    for (int r = 0; r < 6; ++r)
        #pragma unroll
        for (int c = 0; c < 6; ++c) {
            int gh = h0 + r, gw = w0 + c;
            d[r][c] = ((unsigned)gh < 64u && (unsigned)gw < 64u) ? p[gh * 64 + gw] : 0.f;
        }
    float tt[6][6];
    #pragma unroll
    for (int c = 0; c < 6; ++c) {
        float col[6], o[6];
        #pragma unroll
        for (int r = 0; r < 6; ++r) col[r] = d[r][c];
        btform(col, o);
        #pragma unroll
        for (int r = 0; r < 6; ++r) tt[r][c] = o[r];
    }
    int base = (img << 8) + t;
    #pragma unroll
    for (int r = 0; r < 6; ++r) {
        float o[6];
        btform(tt[r], o);
        #pragma unroll
        for (int s = 0; s < 6; ++s)
            g_V[((size_t)(r * 6 + s) * CIN + ci) * NT2 + base] = o[s];
    }
}

// ---------------------------------------------------------------------------
// GEMM: M[xi][co][t] = sum_ci U[xi][ci][co] * V[xi][ci][t]
// Block 64co x 256t, K chunks of 8; thread = 8co x {4l, 128+4l} (LDS.128).
// ---------------------------------------------------------------------------
template<int CO>
__global__ __launch_bounds__(256, 2)
void gemm_wino()
{
    __shared__ float sU[8][64];
    __shared__ float sV[8][256];

    const float* U = Uptr<CO>();
    float*       M = Mptr<CO>();

    const int xi  = blockIdx.z;
    const int co0 = blockIdx.y * 64;
    const int t0  = blockIdx.x * 256;
    const int t   = threadIdx.x;
    const int l   = t & 31;
    const int co8 = (t >> 5) * 8;

    const float* Ub = U + (size_t)xi * CIN * CO;
    const float* Vb = g_V + (size_t)xi * CIN * NT2;

    float acc[8][8];
    #pragma unroll
    for (int j = 0; j < 8; ++j)
        #pragma unroll
        for (int i = 0; i < 8; ++i) acc[j][i] = 0.f;

    for (int k0 = 0; k0 < CIN; k0 += 8) {
        __syncthreads();
        {
            int k = t >> 6, c = t & 63;
            sU[k][c]     = Ub[(size_t)(k0 + k) * CO + co0 + c];
            sU[k + 4][c] = Ub[(size_t)(k0 + k + 4) * CO + co0 + c];
        }
        #pragma unroll
        for (int j = 0; j < 8; ++j)
            sV[j][t] = Vb[(size_t)(k0 + j) * NT2 + t0 + t];
        __syncthreads();

        #pragma unroll
        for (int k = 0; k < 8; ++k) {
            float4 u4a = *(const float4*)&sU[k][co8];
            float4 u4b = *(const float4*)&sU[k][co8 + 4];
            float4 va  = *(const float4*)&sV[k][4 * l];
            float4 vb  = *(const float4*)&sV[k][128 + 4 * l];
            float u[8] = {u4a.x, u4a.y, u4a.z, u4a.w, u4b.x, u4b.y, u4b.z, u4b.w};
            float v[8] = {va.x, va.y, va.z, va.w, vb.x, vb.y, vb.z, vb.w};
            #pragma unroll
            for (int j = 0; j < 8; ++j)
                #pragma unroll
                for (int i = 0; i < 8; ++i)
                    acc[j][i] = fmaf(u[j], v[i], acc[j][i]);
        }
    }

    #pragma unroll
    for (int j = 0; j < 8; ++j) {
        float* mb = M + ((size_t)xi * CO + co0 + co8 + j) * NT2 + t0;
        *(float4*)(mb + 4 * l)       = make_float4(acc[j][0], acc[j][1], acc[j][2], acc[j][3]);
        *(float4*)(mb + 128 + 4 * l) = make_float4(acc[j][4], acc[j][5], acc[j][6], acc[j][7]);
    }
}

// ---------------------------------------------------------------------------
// Output transform Y = A^T M A (6x6 -> 4x4) + BN + ReLU -> NCHW
// A^T rows: [1,1,1,1,1,0],[0,1,-1,2,-2,0],[0,1,1,4,4,0],[0,1,-1,8,-8,1]
// ---------------------------------------------------------------------------
__device__ __forceinline__ void atform(const float* m, float* o)
{
    o[0] = m[0] + m[1] + m[2] + m[3] + m[4];
    o[1] = m[1] - m[2] + 2.f * (m[3] - m[4]);
    o[2] = m[1] + m[2] + 4.f * (m[3] + m[4]);
    o[3] = m[1] - m[2] + 8.f * (m[3] - m[4]) + m[5];
}

template<int CO, bool TO_SBUF>
__global__ void out_wino(const float* __restrict__ bg, const float* __restrict__ bb,
                         const float* __restrict__ bm, const float* __restrict__ bv,
                         float* __restrict__ out_ext)
{
    const float* M = Mptr<CO>();
    int co = blockIdx.y;
    int tg = blockIdx.x * 256 + threadIdx.x;    // 0..1023

    float m[36];
    #pragma unroll
    for (int xi = 0; xi < 36; ++xi)
        m[xi] = M[((size_t)xi * CO + co) * NT2 + tg];

    float z[4][6];
    #pragma unroll
    for (int c = 0; c < 6; ++c) {
        float col[6] = {m[c], m[6 + c], m[12 + c], m[18 + c], m[24 + c], m[30 + c]};
        float o[4];
        atform(col, o);
        #pragma unroll
        for (int r = 0; r < 4; ++r) z[r][c] = o[r];
    }

    float sc = bg[co] * rsqrtf(bv[co] + 1e-5f);
    float bi = bb[co] - bm[co] * sc;

    int img = tg >> 8, tile = tg & 255;
    int ty = tile >> 4, tx = tile & 15;
    float* op = TO_SBUF ? g_sbuf : out_ext;
    float* ob = op + (((size_t)img * CO + co) * HW + 4 * ty) * HW + 4 * tx;

    #pragma unroll
    for (int r = 0; r < 4; ++r) {
        float y[4];
        atform(z[r], y);
        #pragma unroll
        for (int i = 0; i < 4; ++i) {
            float v = fmaf(y[i], sc, bi);
            y[i] = v > 0.f ? v : 0.f;
        }
        *(float4*)(ob + r * HW) = make_float4(y[0], y[1], y[2], y[3]);
    }
}

// ---------------------------------------------------------------------------
// Tail (validated, unchanged)
// ---------------------------------------------------------------------------
__global__ void y2_kernel(const float* __restrict__ ce2)
{
    int nb = blockIdx.x;
    int n = nb >> 6, h = nb & 63, w = threadIdx.x;
    const float* p = ce2 + ((size_t)n * C2 * HW + h) * HW + w;
    float acc = 0.f;
    for (int c = 0; c < C2; ++c) {
        float v = p[(size_t)c * HW * HW];
        acc = fmaf(v, v, acc);
    }
    g_y2[(n * HW + h) * HW + w] = acc;
}

__global__ __launch_bounds__(512)
void wgt_kernel(const float* __restrict__ ce2)
{
    __shared__ float s_oth[8][5][68];
    __shared__ float s_acc[26][4][64];

    int nb = blockIdx.x;
    int n = nb >> 6, h = nb & 63;
    int t = threadIdx.x;
    int cg = t >> 6, w = t & 63;

    float acc[25];
    #pragma unroll
    for (int o = 0; o < 25; ++o) acc[o] = 0.f;
    float x2 = 0.f;

    const float* oth = ce2 + (size_t)n       * C2 * HW * HW;
    const float* c2  = ce2 + (size_t)(2 + n) * C2 * HW * HW;

    for (int c0 = 0; c0 < C2; c0 += 8) {
        __syncthreads();
        for (int e = t; e < 2720; e += 512) {
            int ec  = e / 340;
            int rem = e - ec * 340;
            int rr  = rem / 68;
            int ww  = rem - rr * 68;
            int gh  = h + rr - 2;
            int gw  = ww - 2;
            float v = 0.f;
            if ((unsigned)gh < 64u && (unsigned)gw < 64u)
                v = oth[((size_t)(c0 + ec) * HW + gh) * HW + gw];
            s_oth[ec][rr][ww] = v;
        }
        __syncthreads();

        float cv = c2[((size_t)(c0 + cg) * HW + h) * HW + w];
        x2 = fmaf(cv, cv, x2);
        #pragma unroll
        for (int o = 0; o < 25; ++o)
            acc[o] = fmaf(cv, s_oth[cg][o / 5][w + (o % 5)], acc[o]);
    }

    __syncthreads();
    if (cg >= 4) {
        #pragma unroll
        for (int o = 0; o < 25; ++o) s_acc[o][cg - 4][w] = acc[o];
        s_acc[25][cg - 4][w] = x2;
    }
    __syncthreads();
    if (cg < 4) {
        #pragma unroll
        for (int o = 0; o < 25; ++o) s_acc[o][cg][w] += acc[o];
        s_acc[25][cg][w] += x2;
    }
    __syncthreads();

    if (cg == 0) {
        float X2 = s_acc[25][0][w] + s_acc[25][1][w] + s_acc[25][2][w] + s_acc[25][3][w];
        float inv[25];
        #pragma unroll
        for (int o = 0; o < 25; ++o) {
            float cr = s_acc[o][0][w] + s_acc[o][1][w] + s_acc[o][2][w] + s_acc[o][3][w];
            int gh = h + (o / 5) - 2;
            int gw = w + (o % 5) - 2;
            float y2v = 1e20f;
            if ((unsigned)gh < 64u && (unsigned)gw < 64u)
                y2v = g_y2[(n * HW + gh) * HW + gw];
            float dist = X2 + y2v - 2.f * cr;
            inv[o] = 1.f / (dist + 1e-5f);
        }
        float m = inv[0];
        #pragma unroll
        for (int o = 1; o < 25; ++o) m = fmaxf(m, inv[o]);
        float s = 0.f;
        #pragma unroll
        for (int o = 0; o < 25; ++o) { inv[o] = expf(inv[o] - m); s += inv[o]; }
        float rs = 1.f / s;
        #pragma unroll
        for (int o = 0; o < 25; ++o)
            g_wgt[((o * NPAIR + n) * HW + h) * HW + w] = inv[o] * rs;
    }
}

__global__ __launch_bounds__(256)
void warp_kernel()
{
    __shared__ float s_w25[25][64];
    __shared__ float s_oth[4][5][68];

    int nb = blockIdx.x;
    int n = nb >> 6, h = nb & 63;
    int t = threadIdx.x;

    for (int e = t; e < 1600; e += 256) {
        int o = e >> 6, ww = e & 63;
        s_w25[o][ww] = g_wgt[((o * NPAIR + n) * HW + h) * HW + ww];
    }

    const float* oth = g_sbuf + (size_t)n       * C1 * HW * HW;
    const float* cim = g_sbuf + (size_t)(2 + n) * C1 * HW * HW;
    int cc = t >> 6, w = t & 63;

    for (int c0 = 0; c0 < C1; c0 += 4) {
        __syncthreads();
        for (int e = t; e < 1360; e += 256) {
            int ec  = e / 340;
            int rem = e - ec * 340;
            int rr  = rem / 68;
            int ww  = rem - rr * 68;
            int gh  = h + rr - 2;
            int gw  = ww - 2;
            float v = 0.f;
            if ((unsigned)gh < 64u && (unsigned)gw < 64u)
                v = oth[((size_t)(c0 + ec) * HW + gh) * HW + gw];
            s_oth[ec][rr][ww] = v;
        }
        __syncthreads();

        float civ = cim[((size_t)(c0 + cc) * HW + h) * HW + w];
        float a = 0.f;
        #pragma unroll
        for (int o = 0; o < 25; ++o)
            a = fmaf(s_w25[o][w], s_oth[cc][o / 5][w + (o % 5)], a);
        float res = 0.5f * (civ + a * (1.0f / 25.0f));
        g_final[(((size_t)n * HW + h) * HW + w) * C1 + c0 + cc] = res;
    }
}

__global__ void wt_kernel(const float* __restrict__ lw)
{
    int o = blockIdx.x, c = threadIdx.x;
    g_WT[c * NCLS + o] = lw[o * 256 + c];
}

__global__ __launch_bounds__(128)
void head_kernel(const float* __restrict__ lb, float* __restrict__ xout)
{
    __shared__ float s_x[8][256];
    __shared__ float s_red[128];

    int pg = blockIdx.x;
    int t  = threadIdx.x;

    for (int e = t; e < 2048; e += 128) {
        int pp = e >> 8, c = e & 255;
        s_x[pp][c] = g_final[((size_t)pg * 8 + pp) * 256 + c];
    }
    __syncthreads();

    float acc[8];
    #pragma unroll
    for (int pp = 0; pp < 8; ++pp) acc[pp] = 0.f;

    if (t < NCLS) {
        for (int c = 0; c < 256; ++c) {
            float wv = g_WT[c * NCLS + t];
            #pragma unroll
            for (int pp = 0; pp < 8; ++pp)
                acc[pp] = fmaf(s_x[pp][c], wv, acc[pp]);
        }
        float bias = lb[t];
        #pragma unroll
        for (int pp = 0; pp < 8; ++pp) acc[pp] += bias;
    }

    for (int pp = 0; pp < 8; ++pp) {
        __syncthreads();
        s_red[t] = (t < NCLS) ? acc[pp] : -3.4e38f;
        __syncthreads();
        for (int s = 64; s > 0; s >>= 1) {
            if (t < s) s_red[t] = fmaxf(s_red[t], s_red[t + s]);
            __syncthreads();
        }
        float mx = s_red[0];
        __syncthreads();
        s_red[t] = (t < NCLS) ? expf(acc[pp] - mx) : 0.f;
        __syncthreads();
        for (int s = 64; s > 0; s >>= 1) {
            if (t < s) s_red[t] += s_red[t + s];
            __syncthreads();
        }
        float lse = mx + logf(s_red[0]);

        int pix = pg * 8 + pp;
        int n = pix >> 12, h = (pix >> 6) & 63, w = pix & 63;
        if (t < NCLS)
            xout[(((size_t)n * NCLS + t) * HW + h) * HW + w] = acc[pp] - lse;
    }
}

// ---------------------------------------------------------------------------
extern "C" void kernel_launch(void* const* d_in, const int* in_sizes, int n_in,
                              void* d_out, int out_size)
{
    const float* clip  = (const float*)d_in[0];
    const float* embW  = (const float*)d_in[2];
    const float* eg    = (const float*)d_in[3];
    const float* eb    = (const float*)d_in[4];
    const float* em    = (const float*)d_in[5];
    const float* ev    = (const float*)d_in[6];
    const float* emb2W = (const float*)d_in[7];
    const float* e2g   = (const float*)d_in[8];
    const float* e2b   = (const float*)d_in[9];
    const float* e2m   = (const float*)d_in[10];
    const float* e2v   = (const float*)d_in[11];
    const float* lastW = (const float*)d_in[12];
    const float* lastb = (const float*)d_in[13];

    float* xout = (float*)d_out;
    float* ce2  = (float*)d_out + X_ELEMS;

    prep_u<C1><<<CIN, C1>>>(embW);
    prep_u<C2><<<CIN, C2>>>(emb2W);
    prep_v<<<NIMG * CIN, 256>>>(clip);

    gemm_wino<C2><<<dim3(NT2 / 256, C2 / 64, 36), 256>>>();
    gemm_wino<C1><<<dim3(NT2 / 256, C1 / 64, 36), 256>>>();

    out_wino<C2, false><<<dim3(NT2 / 256, C2), 256>>>(e2g, e2b, e2m, e2v, ce2);
    out_wino<C1, true ><<<dim3(NT2 / 256, C1), 256>>>(eg, eb, em, ev, nullptr);

    y2_kernel <<<NPAIR * HW, 64>>>(ce2);
    wgt_kernel<<<NPAIR * HW, 512>>>(ce2);
    warp_kernel<<<NPAIR * HW, 256>>>();
    wt_kernel  <<<NCLS, 256>>>(lastW);
    head_kernel<<<(NPAIR * HW * HW) / 8, 128>>>(lastb, xout);
}

// round 15
// speedup vs baseline: 20.3537x; 1.1928x over previous
#include <cuda_runtime.h>
#include <cuda_bf16.h>
#include <math.h>

// ---------------------------------------------------------------------------
// WarpNet — Round 15: Winograd F(4x4,3x3) + bf16x3 mma.sync GEMMs.
//   U repacked to R5-validated A-fragment order (bf16 hi/lo, device-resident).
//   V transposed/split to k-contiguous packed bf16 (Vpk[xi][t][k]).
//   GEMM: 128co x 128t block, K=512 in 16 chunks, double-buffered B tiles,
//   D ~= Uh*Vh + Ul*Vh + Uh*Vl.  All scratch via device symbols ONLY (ATS).
// ---------------------------------------------------------------------------

#define NIMG   4
#define CIN    512
#define HW     64
#define C1     256
#define C2     128
#define NCLS   124
#define NPAIR  2
#define NT2    1024
#define KCH    16               // K chunks of 32
#define X_ELEMS (2 * NCLS * HW * HW)

typedef unsigned int u32;

// ---------------- scratch (device globals; device-code access ONLY) ---------
__device__ float g_sbuf [NIMG * C1 * HW * HW];
__device__ float g_y2   [NPAIR * HW * HW];
__device__ float g_wgt  [25 * NPAIR * HW * HW];
__device__ float g_final[NPAIR * HW * HW * C1];
__device__ float g_WT   [256 * NCLS];
__device__ float g_V [36 * CIN * NT2];
__device__ float g_U1[36 * CIN * C1];
__device__ float g_U2[36 * CIN * C2];
__device__ float g_M1[36 * C1 * NT2];
__device__ float g_M2[36 * C2 * NT2];
__device__ __align__(16) u32 g_A1h[36 * 2 * KCH * 2048];
__device__ __align__(16) u32 g_A1l[36 * 2 * KCH * 2048];
__device__ __align__(16) u32 g_A2h[36 * 1 * KCH * 2048];
__device__ __align__(16) u32 g_A2l[36 * 1 * KCH * 2048];
__device__ __align__(16) u32 g_Vpk[36 * NT2 * CIN];

template<int CO> __device__ __forceinline__ float* Uptr() { return (CO == C1) ? g_U1 : g_U2; }
template<int CO> __device__ __forceinline__ float* Mptr() { return (CO == C1) ? g_M1 : g_M2; }
template<int CO> __device__ __forceinline__ u32* Ahp() { return (CO == C1) ? g_A1h : g_A2h; }
template<int CO> __device__ __forceinline__ u32* Alp() { return (CO == C1) ? g_A1l : g_A2l; }

// ---------------- PTX helpers -------------------------------------------------
__device__ __forceinline__ u32 smem_u32(const void* p) {
    u32 a;
    asm("{ .reg .u64 t; cvta.to.shared.u64 t, %1; cvt.u32.u64 %0, t; }"
        : "=r"(a) : "l"(p));
    return a;
}
__device__ __forceinline__ void ldmx2(u32& r0, u32& r1, u32 addr) {
    asm volatile("ldmatrix.sync.aligned.m8n8.x2.shared.b16 {%0,%1}, [%2];"
        : "=r"(r0), "=r"(r1) : "r"(addr));
}
__device__ __forceinline__ void mma_bf16(float* d, const u32* a, const u32* b) {
    asm volatile("mma.sync.aligned.m16n8k16.row.col.f32.bf16.bf16.f32 "
        "{%0,%1,%2,%3}, {%4,%5,%6,%7}, {%8,%9}, {%0,%1,%2,%3};"
        : "+f"(d[0]), "+f"(d[1]), "+f"(d[2]), "+f"(d[3])
        : "r"(a[0]), "r"(a[1]), "r"(a[2]), "r"(a[3]), "r"(b[0]), "r"(b[1]));
}
__device__ __forceinline__ u32 bfsplit(float v, float& rem) {
    __nv_bfloat16 h = __float2bfloat16(v);
    rem = v - __bfloat162float(h);
    return (u32)__bfloat16_as_ushort(h);
}

// ---------------------------------------------------------------------------
// Winograd transforms (validated R14)
// ---------------------------------------------------------------------------
__device__ __forceinline__ void gxform(const float a, const float b, const float c,
                                       float* o)
{
    o[0] = 0.25f * a;
    o[1] = -(a + b + c) * (1.f / 6.f);
    o[2] = -(a - b + c) * (1.f / 6.f);
    o[3] = a * (1.f / 24.f) + b * (1.f / 12.f) + c * (1.f / 6.f);
    o[4] = a * (1.f / 24.f) - b * (1.f / 12.f) + c * (1.f / 6.f);
    o[5] = c;
}

template<int CO>
__global__ void prep_u(const float* __restrict__ W)
{
    float* U = Uptr<CO>();
    int ci = blockIdx.x, co = threadIdx.x;
    const float* g = W + ((size_t)co * CIN + ci) * 9;
    float t6[6][3];
    #pragma unroll
    for (int c = 0; c < 3; ++c) {
        float col[6];
        gxform(g[c], g[3 + c], g[6 + c], col);
        #pragma unroll
        for (int r = 0; r < 6; ++r) t6[r][c] = col[r];
    }
    #pragma unroll
    for (int r = 0; r < 6; ++r) {
        float u[6];
        gxform(t6[r][0], t6[r][1], t6[r][2], u);
        #pragma unroll
        for (int s = 0; s < 6; ++s)
            U[((size_t)(r * 6 + s) * CIN + ci) * CO + co] = u[s];
    }
}

__device__ __forceinline__ void btform(const float* d, float* o)
{
    o[0] = 4.f * d[0] - 5.f * d[2] + d[4];
    o[1] = -4.f * d[1] - 4.f * d[2] + d[3] + d[4];
    o[2] =  4.f * d[1] - 4.f * d[2] - d[3] + d[4];
    o[3] = -2.f * d[1] - d[2] + 2.f * d[3] + d[4];
    o[4] =  2.f * d[1] - d[2] - 2.f * d[3] + d[4];
    o[5] =  4.f * d[1] - 5.f * d[3] + d[5];
}

__global__ __launch_bounds__(256)
void prep_v(const float* __restrict__ x)
{
    int b = blockIdx.x;
    int img = b >> 9, ci = b & 511;
    int t = threadIdx.x;
    int ty = t >> 4, tx = t & 15;
    const float* p = x + ((size_t)img * CIN + ci) * HW * HW;
    int h0 = 4 * ty - 1, w0 = 4 * tx - 1;

    float d[6][6];
    #pragma unroll
    for (int r = 0; r < 6; ++r)
        #pragma unroll
        for (int c = 0; c < 6; ++c) {
            int gh = h0 + r, gw = w0 + c;
            d[r][c] = ((unsigned)gh < 64u && (unsigned)gw < 64u) ? p[gh * 64 + gw] : 0.f;
        }
    float tt[6][6];
    #pragma unroll
    for (int c = 0; c < 6; ++c) {
        float col[6], o[6];
        #pragma unroll
        for (int r = 0; r < 6; ++r) col[r] = d[r][c];
        btform(col, o);
        #pragma unroll
        for (int r = 0; r < 6; ++r) tt[r][c] = o[r];
    }
    int base = (img << 8) + t;
    #pragma unroll
    for (int r = 0; r < 6; ++r) {
        float o[6];
        btform(tt[r], o);
        #pragma unroll
        for (int s = 0; s < 6; ++s)
            g_V[((size_t)(r * 6 + s) * CIN + ci) * NT2 + base] = o[s];
    }
}

// ---------------------------------------------------------------------------
// Repack U -> bf16 hi/lo in mma A-fragment order.
// Block = (c, cz, xi); 256 thr. Out u32 idx: blkbase + wm*512 + q*32 + lane.
//   co = cz*128 + wm*32 + f*16 + (lane>>2) + (reg&1)*8
//   k  = c*32 + kb*16 + 2*(lane&3) + (reg>>1)*8  (+1 in high half)
// ---------------------------------------------------------------------------
template<int CO>
__global__ __launch_bounds__(256)
void repack_a()
{
    __shared__ float sUc[32][132];
    const float* U = Uptr<CO>();
    u32* Ah = Ahp<CO>();
    u32* Al = Alp<CO>();

    int c  = blockIdx.x;
    int cz = blockIdx.y;
    int xi = blockIdx.z;
    int t  = threadIdx.x;

    #pragma unroll
    for (int r = 0; r < 16; ++r) {
        int slot = t + 256 * r;
        int k = slot >> 7, co = slot & 127;
        sUc[k][co] = U[((size_t)xi * CIN + c * 32 + k) * CO + cz * 128 + co];
    }
    __syncthreads();

    size_t base = ((size_t)(xi * (CO / 128) + cz) * KCH + c) * 2048;
    #pragma unroll
    for (int r = 0; r < 8; ++r) {
        int slot = t + 256 * r;
        int lane = slot & 31, q = (slot >> 5) & 15, wm = slot >> 9;
        int kb = q >> 3, f = (q >> 2) & 1, reg = q & 3;
        int co = wm * 32 + f * 16 + (lane >> 2) + (reg & 1) * 8;
        int k  = kb * 16 + 2 * (lane & 3) + (reg >> 1) * 8;
        float r0, r1;
        u32 h0 = bfsplit(sUc[k][co], r0);
        u32 h1 = bfsplit(sUc[k + 1][co], r1);
        __nv_bfloat16 l0 = __float2bfloat16(r0);
        __nv_bfloat16 l1 = __float2bfloat16(r1);
        Ah[base + slot] = h0 | (h1 << 16);
        Al[base + slot] = (u32)__bfloat16_as_ushort(l0) |
                          ((u32)__bfloat16_as_ushort(l1) << 16);
    }
}

// ---------------------------------------------------------------------------
// Transpose + split V: g_V[xi][k][t] fp32 -> g_Vpk[xi][t][k] (hi | lo<<16)
// ---------------------------------------------------------------------------
__global__ __launch_bounds__(256)
void vsplit()
{
    __shared__ float sT[32][129];
    int t0 = blockIdx.x * 128;
    int k0 = blockIdx.y * 32;
    int xi = blockIdx.z;
    int t  = threadIdx.x;

    #pragma unroll
    for (int r = 0; r < 16; ++r) {
        int slot = t + 256 * r;
        int kk = slot >> 7, tc = slot & 127;
        sT[kk][tc] = g_V[((size_t)xi * CIN + k0 + kk) * NT2 + t0 + tc];
    }
    __syncthreads();
    #pragma unroll
    for (int r = 0; r < 16; ++r) {
        int slot = t + 256 * r;
        int tl = slot >> 5, kl = slot & 31;
        float v = sT[kl][tl];
        float rem;
        u32 h = bfsplit(v, rem);
        __nv_bfloat16 l = __float2bfloat16(rem);
        g_Vpk[((size_t)xi * NT2 + t0 + tl) * CIN + k0 + kl] =
            h | ((u32)__bfloat16_as_ushort(l) << 16);
    }
}

// ---------------------------------------------------------------------------
// GEMM via mma.sync: M[xi][co][t] = sum_k U[k][co] * V[k][t]  (bf16x3)
// Block 128co x 128t; 8 warps (wm 0-3, wn 0-1); K chunks of 32, double buf B.
// ---------------------------------------------------------------------------
#define B_TILE 8192

template<int CO>
__global__ __launch_bounds__(256)
void gemm_mma()
{
    __shared__ u32 sB[2 * 2 * 2048];     // [buf][hi/lo][8KB]
    const u32 sb = smem_u32(sB);

    const u32* Ah = Ahp<CO>();
    const u32* Al = Alp<CO>();
    float*     M  = Mptr<CO>();

    const int t   = threadIdx.x;
    const int l   = t & 31;
    const int wid = t >> 5;
    const int wm  = wid & 3;
    const int wn  = wid >> 2;
    const int t0  = blockIdx.x * 128;
    const int cz  = blockIdx.y;
    const int xi  = blockIdx.z;

    float acc[2][8][4];
    #pragma unroll
    for (int f = 0; f < 2; ++f)
        #pragma unroll
        for (int nf = 0; nf < 8; ++nf)
            #pragma unroll
            for (int r = 0; r < 4; ++r) acc[f][nf][r] = 0.f;

    const size_t abase = ((size_t)(xi * (CO / 128) + cz) * KCH) * 2048 + wm * 512 + l;
    const u32* Vb = g_Vpk + (size_t)xi * NT2 * CIN;
    const u32 lm_base = sb + (u32)(wn * 4096 + ((l >> 3) & 1) * 128 + (l & 7) * 16);

    for (int c = 0; c < KCH; ++c) {
        const int buf = c & 1;
        const u32 bB = sb + (u32)(buf * 16384);

        // ---- B build: coalesced uint4 from Vpk, unpack hi/lo, 8x8 blocks ----
        #pragma unroll
        for (int rep = 0; rep < 4; ++rep) {
            int slot = t + rep * 256;
            int bn = slot >> 3, kq = slot & 7;
            uint4 v4 = *(const uint4*)&Vb[(size_t)(t0 + bn) * CIN + c * 32 + kq * 4];
            u32 h01 = (v4.x & 0xFFFFu) | (v4.y << 16);
            u32 l01 = (v4.x >> 16) | (v4.y & 0xFFFF0000u);
            u32 h23 = (v4.z & 0xFFFFu) | (v4.w << 16);
            u32 l23 = (v4.z >> 16) | (v4.w & 0xFFFF0000u);
            u32 ad = bB + (u32)(((bn >> 3) * 4 + (kq >> 1)) * 128 +
                                (bn & 7) * 16 + (kq & 1) * 8);
            asm volatile("st.shared.v2.b32 [%0], {%1,%2};" :: "r"(ad), "r"(h01), "r"(h23) : "memory");
            asm volatile("st.shared.v2.b32 [%0], {%1,%2};" :: "r"(ad + B_TILE), "r"(l01), "r"(l23) : "memory");
        }

        // ---- A fragments (coalesced, L2-resident) ----
        u32 ah[16], al[16];
        {
            const u32* aph = Ah + abase + (size_t)c * 2048;
            const u32* apl = Al + abase + (size_t)c * 2048;
            #pragma unroll
            for (int q = 0; q < 16; ++q) { ah[q] = aph[q * 32]; al[q] = apl[q * 32]; }
        }
        __syncthreads();

        const u32 lb = lm_base + (u32)(buf * 16384);
        #pragma unroll
        for (int kb = 0; kb < 2; ++kb) {
            #pragma unroll
            for (int nf = 0; nf < 8; ++nf) {
                u32 a = lb + (u32)(nf * 512 + kb * 256);
                u32 bh[2], bl_[2];
                ldmx2(bh[0], bh[1], a);
                ldmx2(bl_[0], bl_[1], a + B_TILE);
                #pragma unroll
                for (int f = 0; f < 2; ++f) {
                    const u32* a_h = ah + kb * 8 + f * 4;
                    const u32* a_l = al + kb * 8 + f * 4;
                    mma_bf16(acc[f][nf], a_h, bh);
                    mma_bf16(acc[f][nf], a_l, bh);
                    mma_bf16(acc[f][nf], a_h, bl_);
                }
            }
        }
        __syncthreads();   // protect B buffer (other half) WAR
    }

    #pragma unroll
    for (int f = 0; f < 2; ++f) {
        int co = cz * 128 + wm * 32 + f * 16 + (l >> 2);
        #pragma unroll
        for (int nf = 0; nf < 8; ++nf) {
            int n0 = t0 + wn * 64 + nf * 8 + 2 * (l & 3);
            float* mb = M + ((size_t)xi * CO + co) * NT2 + n0;
            *(float2*)mb = make_float2(acc[f][nf][0], acc[f][nf][1]);
            *(float2*)(mb + 8 * (size_t)NT2) = make_float2(acc[f][nf][2], acc[f][nf][3]);
        }
    }
}

// ---------------------------------------------------------------------------
// Output transform Y = A^T M A (6x6 -> 4x4) + BN + ReLU -> NCHW
// ---------------------------------------------------------------------------
__device__ __forceinline__ void atform(const float* m, float* o)
{
    o[0] = m[0] + m[1] + m[2] + m[3] + m[4];
    o[1] = m[1] - m[2] + 2.f * (m[3] - m[4]);
    o[2] = m[1] + m[2] + 4.f * (m[3] + m[4]);
    o[3] = m[1] - m[2] + 8.f * (m[3] - m[4]) + m[5];
}

template<int CO, bool TO_SBUF>
__global__ void out_wino(const float* __restrict__ bg, const float* __restrict__ bb,
                         const float* __restrict__ bm, const float* __restrict__ bv,
                         float* __restrict__ out_ext)
{
    const float* M = Mptr<CO>();
    int co = blockIdx.y;
    int tg = blockIdx.x * 256 + threadIdx.x;

    float m[36];
    #pragma unroll
    for (int xi = 0; xi < 36; ++xi)
        m[xi] = M[((size_t)xi * CO + co) * NT2 + tg];

    float z[4][6];
    #pragma unroll
    for (int c = 0; c < 6; ++c) {
        float col[6] = {m[c], m[6 + c], m[12 + c], m[18 + c], m[24 + c], m[30 + c]};
        float o[4];
        atform(col, o);
        #pragma unroll
        for (int r = 0; r < 4; ++r) z[r][c] = o[r];
    }

    float sc = bg[co] * rsqrtf(bv[co] + 1e-5f);
    float bi = bb[co] - bm[co] * sc;

    int img = tg >> 8, tile = tg & 255;
    int ty = tile >> 4, tx = tile & 15;
    float* op = TO_SBUF ? g_sbuf : out_ext;
    float* ob = op + (((size_t)img * CO + co) * HW + 4 * ty) * HW + 4 * tx;

    #pragma unroll
    for (int r = 0; r < 4; ++r) {
        float y[4];
        atform(z[r], y);
        #pragma unroll
        for (int i = 0; i < 4; ++i) {
            float v = fmaf(y[i], sc, bi);
            y[i] = v > 0.f ? v : 0.f;
        }
        *(float4*)(ob + r * HW) = make_float4(y[0], y[1], y[2], y[3]);
    }
}

// ---------------------------------------------------------------------------
// Tail (validated, unchanged)
// ---------------------------------------------------------------------------
__global__ void y2_kernel(const float* __restrict__ ce2)
{
    int nb = blockIdx.x;
    int n = nb >> 6, h = nb & 63, w = threadIdx.x;
    const float* p = ce2 + ((size_t)n * C2 * HW + h) * HW + w;
    float acc = 0.f;
    for (int c = 0; c < C2; ++c) {
        float v = p[(size_t)c * HW * HW];
        acc = fmaf(v, v, acc);
    }
    g_y2[(n * HW + h) * HW + w] = acc;
}

__global__ __launch_bounds__(512)
void wgt_kernel(const float* __restrict__ ce2)
{
    __shared__ float s_oth[8][5][68];
    __shared__ float s_acc[26][4][64];

    int nb = blockIdx.x;
    int n = nb >> 6, h = nb & 63;
    int t = threadIdx.x;
    int cg = t >> 6, w = t & 63;

    float acc[25];
    #pragma unroll
    for (int o = 0; o < 25; ++o) acc[o] = 0.f;
    float x2 = 0.f;

    const float* oth = ce2 + (size_t)n       * C2 * HW * HW;
    const float* c2  = ce2 + (size_t)(2 + n) * C2 * HW * HW;

    for (int c0 = 0; c0 < C2; c0 += 8) {
        __syncthreads();
        for (int e = t; e < 2720; e += 512) {
            int ec  = e / 340;
            int rem = e - ec * 340;
            int rr  = rem / 68;
            int ww  = rem - rr * 68;
            int gh  = h + rr - 2;
            int gw  = ww - 2;
            float v = 0.f;
            if ((unsigned)gh < 64u && (unsigned)gw < 64u)
                v = oth[((size_t)(c0 + ec) * HW + gh) * HW + gw];
            s_oth[ec][rr][ww] = v;
        }
        __syncthreads();

        float cv = c2[((size_t)(c0 + cg) * HW + h) * HW + w];
        x2 = fmaf(cv, cv, x2);
        #pragma unroll
        for (int o = 0; o < 25; ++o)
            acc[o] = fmaf(cv, s_oth[cg][o / 5][w + (o % 5)], acc[o]);
    }

    __syncthreads();
    if (cg >= 4) {
        #pragma unroll
        for (int o = 0; o < 25; ++o) s_acc[o][cg - 4][w] = acc[o];
        s_acc[25][cg - 4][w] = x2;
    }
    __syncthreads();
    if (cg < 4) {
        #pragma unroll
        for (int o = 0; o < 25; ++o) s_acc[o][cg][w] += acc[o];
        s_acc[25][cg][w] += x2;
    }
    __syncthreads();

    if (cg == 0) {
        float X2 = s_acc[25][0][w] + s_acc[25][1][w] + s_acc[25][2][w] + s_acc[25][3][w];
        float inv[25];
        #pragma unroll
        for (int o = 0; o < 25; ++o) {
            float cr = s_acc[o][0][w] + s_acc[o][1][w] + s_acc[o][2][w] + s_acc[o][3][w];
            int gh = h + (o / 5) - 2;
            int gw = w + (o % 5) - 2;
            float y2v = 1e20f;
            if ((unsigned)gh < 64u && (unsigned)gw < 64u)
                y2v = g_y2[(n * HW + gh) * HW + gw];
            float dist = X2 + y2v - 2.f * cr;
            inv[o] = 1.f / (dist + 1e-5f);
        }
        float m = inv[0];
        #pragma unroll
        for (int o = 1; o < 25; ++o) m = fmaxf(m, inv[o]);
        float s = 0.f;
        #pragma unroll
        for (int o = 0; o < 25; ++o) { inv[o] = expf(inv[o] - m); s += inv[o]; }
        float rs = 1.f / s;
        #pragma unroll
        for (int o = 0; o < 25; ++o)
            g_wgt[((o * NPAIR + n) * HW + h) * HW + w] = inv[o] * rs;
    }
}

__global__ __launch_bounds__(256)
void warp_kernel()
{
    __shared__ float s_w25[25][64];
    __shared__ float s_oth[4][5][68];

    int nb = blockIdx.x;
    int n = nb >> 6, h = nb & 63;
    int t = threadIdx.x;

    for (int e = t; e < 1600; e += 256) {
        int o = e >> 6, ww = e & 63;
        s_w25[o][ww] = g_wgt[((o * NPAIR + n) * HW + h) * HW + ww];
    }

    const float* oth = g_sbuf + (size_t)n       * C1 * HW * HW;
    const float* cim = g_sbuf + (size_t)(2 + n) * C1 * HW * HW;
    int cc = t >> 6, w = t & 63;

    for (int c0 = 0; c0 < C1; c0 += 4) {
        __syncthreads();
        for (int e = t; e < 1360; e += 256) {
            int ec  = e / 340;
            int rem = e - ec * 340;
            int rr  = rem / 68;
            int ww  = rem - rr * 68;
            int gh  = h + rr - 2;
            int gw  = ww - 2;
            float v = 0.f;
            if ((unsigned)gh < 64u && (unsigned)gw < 64u)
                v = oth[((size_t)(c0 + ec) * HW + gh) * HW + gw];
            s_oth[ec][rr][ww] = v;
        }
        __syncthreads();

        float civ = cim[((size_t)(c0 + cc) * HW + h) * HW + w];
        float a = 0.f;
        #pragma unroll
        for (int o = 0; o < 25; ++o)
            a = fmaf(s_w25[o][w], s_oth[cc][o / 5][w + (o % 5)], a);
        float res = 0.5f * (civ + a * (1.0f / 25.0f));
        g_final[(((size_t)n * HW + h) * HW + w) * C1 + c0 + cc] = res;
    }
}

__global__ void wt_kernel(const float* __restrict__ lw)
{
    int o = blockIdx.x, c = threadIdx.x;
    g_WT[c * NCLS + o] = lw[o * 256 + c];
}

__global__ __launch_bounds__(128)
void head_kernel(const float* __restrict__ lb, float* __restrict__ xout)
{
    __shared__ float s_x[8][256];
    __shared__ float s_red[128];

    int pg = blockIdx.x;
    int t  = threadIdx.x;

    for (int e = t; e < 2048; e += 128) {
        int pp = e >> 8, c = e & 255;
        s_x[pp][c] = g_final[((size_t)pg * 8 + pp) * 256 + c];
    }
    __syncthreads();

    float acc[8];
    #pragma unroll
    for (int pp = 0; pp < 8; ++pp) acc[pp] = 0.f;

    if (t < NCLS) {
        for (int c = 0; c < 256; ++c) {
            float wv = g_WT[c * NCLS + t];
            #pragma unroll
            for (int pp = 0; pp < 8; ++pp)
                acc[pp] = fmaf(s_x[pp][c], wv, acc[pp]);
        }
        float bias = lb[t];
        #pragma unroll
        for (int pp = 0; pp < 8; ++pp) acc[pp] += bias;
    }

    for (int pp = 0; pp < 8; ++pp) {
        __syncthreads();
        s_red[t] = (t < NCLS) ? acc[pp] : -3.4e38f;
        __syncthreads();
        for (int s = 64; s > 0; s >>= 1) {
            if (t < s) s_red[t] = fmaxf(s_red[t], s_red[t + s]);
            __syncthreads();
        }
        float mx = s_red[0];
        __syncthreads();
        s_red[t] = (t < NCLS) ? expf(acc[pp] - mx) : 0.f;
        __syncthreads();
        for (int s = 64; s > 0; s >>= 1) {
            if (t < s) s_red[t] += s_red[t + s];
            __syncthreads();
        }
        float lse = mx + logf(s_red[0]);

        int pix = pg * 8 + pp;
        int n = pix >> 12, h = (pix >> 6) & 63, w = pix & 63;
        if (t < NCLS)
            xout[(((size_t)n * NCLS + t) * HW + h) * HW + w] = acc[pp] - lse;
    }
}

// ---------------------------------------------------------------------------
extern "C" void kernel_launch(void* const* d_in, const int* in_sizes, int n_in,
                              void* d_out, int out_size)
{
    const float* clip  = (const float*)d_in[0];
    const float* embW  = (const float*)d_in[2];
    const float* eg    = (const float*)d_in[3];
    const float* eb    = (const float*)d_in[4];
    const float* em    = (const float*)d_in[5];
    const float* ev    = (const float*)d_in[6];
    const float* emb2W = (const float*)d_in[7];
    const float* e2g   = (const float*)d_in[8];
    const float* e2b   = (const float*)d_in[9];
    const float* e2m   = (const float*)d_in[10];
    const float* e2v   = (const float*)d_in[11];
    const float* lastW = (const float*)d_in[12];
    const float* lastb = (const float*)d_in[13];

    float* xout = (float*)d_out;
    float* ce2  = (float*)d_out + X_ELEMS;

    prep_u<C1><<<CIN, C1>>>(embW);
    prep_u<C2><<<CIN, C2>>>(emb2W);
    prep_v<<<NIMG * CIN, 256>>>(clip);

    repack_a<C1><<<dim3(KCH, 2, 36), 256>>>();
    repack_a<C2><<<dim3(KCH, 1, 36), 256>>>();
    vsplit<<<dim3(NT2 / 128, CIN / 32, 36), 256>>>();

    gemm_mma<C2><<<dim3(NT2 / 128, 1, 36), 256>>>();
    gemm_mma<C1><<<dim3(NT2 / 128, 2, 36), 256>>>();

    out_wino<C2, false><<<dim3(NT2 / 256, C2), 256>>>(e2g, e2b, e2m, e2v, ce2);
    out_wino<C1, true ><<<dim3(NT2 / 256, C1), 256>>>(eg, eb, em, ev, nullptr);

    y2_kernel <<<NPAIR * HW, 64>>>(ce2);
    wgt_kernel<<<NPAIR * HW, 512>>>(ce2);
    warp_kernel<<<NPAIR * HW, 256>>>();
    wt_kernel  <<<NCLS, 256>>>(lastW);
    head_kernel<<<(NPAIR * HW * HW) / 8, 128>>>(lastb, xout);
}

// round 16
// speedup vs baseline: 24.6287x; 1.2100x over previous
#include <cuda_runtime.h>
#include <cuda_bf16.h>
#include <math.h>

// ---------------------------------------------------------------------------
// WarpNet — Round 16: F(4x4,3x3) wino + bf16x3 HMMA GEMMs; fused V transform
// (prep_v writes packed bf16 Vpk[xi][t][k] directly); 512-thr warp_kernel;
// shuffle-batched head reductions. Scratch via device symbols ONLY (ATS).
// ---------------------------------------------------------------------------

#define NIMG   4
#define CIN    512
#define HW     64
#define C1     256
#define C2     128
#define NCLS   124
#define NPAIR  2
#define NT2    1024
#define KCH    16
#define X_ELEMS (2 * NCLS * HW * HW)

typedef unsigned int u32;

// ---------------- scratch (device globals; device-code access ONLY) ---------
__device__ float g_sbuf [NIMG * C1 * HW * HW];
__device__ float g_y2   [NPAIR * HW * HW];
__device__ float g_wgt  [25 * NPAIR * HW * HW];
__device__ float g_final[NPAIR * HW * HW * C1];
__device__ float g_WT   [256 * NCLS];
__device__ float g_U1[36 * CIN * C1];
__device__ float g_U2[36 * CIN * C2];
__device__ float g_M1[36 * C1 * NT2];
__device__ float g_M2[36 * C2 * NT2];
__device__ __align__(16) u32 g_A1h[36 * 2 * KCH * 2048];
__device__ __align__(16) u32 g_A1l[36 * 2 * KCH * 2048];
__device__ __align__(16) u32 g_A2h[36 * 1 * KCH * 2048];
__device__ __align__(16) u32 g_A2l[36 * 1 * KCH * 2048];
__device__ __align__(16) u32 g_Vpk[36 * NT2 * CIN];

template<int CO> __device__ __forceinline__ float* Uptr() { return (CO == C1) ? g_U1 : g_U2; }
template<int CO> __device__ __forceinline__ float* Mptr() { return (CO == C1) ? g_M1 : g_M2; }
template<int CO> __device__ __forceinline__ u32* Ahp() { return (CO == C1) ? g_A1h : g_A2h; }
template<int CO> __device__ __forceinline__ u32* Alp() { return (CO == C1) ? g_A1l : g_A2l; }

// ---------------- PTX helpers -------------------------------------------------
__device__ __forceinline__ u32 smem_u32(const void* p) {
    u32 a;
    asm("{ .reg .u64 t; cvta.to.shared.u64 t, %1; cvt.u32.u64 %0, t; }"
        : "=r"(a) : "l"(p));
    return a;
}
__device__ __forceinline__ void ldmx2(u32& r0, u32& r1, u32 addr) {
    asm volatile("ldmatrix.sync.aligned.m8n8.x2.shared.b16 {%0,%1}, [%2];"
        : "=r"(r0), "=r"(r1) : "r"(addr));
}
__device__ __forceinline__ void mma_bf16(float* d, const u32* a, const u32* b) {
    asm volatile("mma.sync.aligned.m16n8k16.row.col.f32.bf16.bf16.f32 "
        "{%0,%1,%2,%3}, {%4,%5,%6,%7}, {%8,%9}, {%0,%1,%2,%3};"
        : "+f"(d[0]), "+f"(d[1]), "+f"(d[2]), "+f"(d[3])
        : "r"(a[0]), "r"(a[1]), "r"(a[2]), "r"(a[3]), "r"(b[0]), "r"(b[1]));
}
__device__ __forceinline__ u32 bfsplit(float v, float& rem) {
    __nv_bfloat16 h = __float2bfloat16(v);
    rem = v - __bfloat162float(h);
    return (u32)__bfloat16_as_ushort(h);
}

// ---------------------------------------------------------------------------
// Winograd transforms (validated)
// ---------------------------------------------------------------------------
__device__ __forceinline__ void gxform(const float a, const float b, const float c,
                                       float* o)
{
    o[0] = 0.25f * a;
    o[1] = -(a + b + c) * (1.f / 6.f);
    o[2] = -(a - b + c) * (1.f / 6.f);
    o[3] = a * (1.f / 24.f) + b * (1.f / 12.f) + c * (1.f / 6.f);
    o[4] = a * (1.f / 24.f) - b * (1.f / 12.f) + c * (1.f / 6.f);
    o[5] = c;
}

template<int CO>
__global__ void prep_u(const float* __restrict__ W)
{
    float* U = Uptr<CO>();
    int ci = blockIdx.x, co = threadIdx.x;
    const float* g = W + ((size_t)co * CIN + ci) * 9;
    float t6[6][3];
    #pragma unroll
    for (int c = 0; c < 3; ++c) {
        float col[6];
        gxform(g[c], g[3 + c], g[6 + c], col);
        #pragma unroll
        for (int r = 0; r < 6; ++r) t6[r][c] = col[r];
    }
    #pragma unroll
    for (int r = 0; r < 6; ++r) {
        float u[6];
        gxform(t6[r][0], t6[r][1], t6[r][2], u);
        #pragma unroll
        for (int s = 0; s < 6; ++s)
            U[((size_t)(r * 6 + s) * CIN + ci) * CO + co] = u[s];
    }
}

__device__ __forceinline__ void btform(const float* d, float* o)
{
    o[0] = 4.f * d[0] - 5.f * d[2] + d[4];
    o[1] = -4.f * d[1] - 4.f * d[2] + d[3] + d[4];
    o[2] =  4.f * d[1] - 4.f * d[2] - d[3] + d[4];
    o[3] = -2.f * d[1] - d[2] + 2.f * d[3] + d[4];
    o[4] =  2.f * d[1] - d[2] - 2.f * d[3] + d[4];
    o[5] =  4.f * d[1] - 5.f * d[3] + d[5];
}

// ---------------------------------------------------------------------------
// Fused input transform + transpose + bf16-split:
//   block = (tgrp, cig, img); thread = (ci_l = t>>3, tl = t&7).
//   Writes g_Vpk[(xi*NT2 + img*256 + tile)*CIN + ci] packed (hi | lo<<16).
// ---------------------------------------------------------------------------
__global__ __launch_bounds__(256)
void prep_v_pk(const float* __restrict__ x)
{
    __shared__ float sM[8][36][33];

    int tgrp = blockIdx.x;           // 0..31
    int cig  = blockIdx.y;           // 0..15
    int img  = blockIdx.z;           // 0..3
    int t    = threadIdx.x;
    int ci_l = t >> 3, tl = t & 7;
    int tile = tgrp * 8 + tl;
    int ty = tile >> 4, tx = tile & 15;
    int ci = cig * 32 + ci_l;

    const float* p = x + ((size_t)img * CIN + ci) * HW * HW;
    int h0 = 4 * ty - 1, w0 = 4 * tx - 1;

    float d[6][6];
    #pragma unroll
    for (int r = 0; r < 6; ++r)
        #pragma unroll
        for (int c = 0; c < 6; ++c) {
            int gh = h0 + r, gw = w0 + c;
            d[r][c] = ((unsigned)gh < 64u && (unsigned)gw < 64u) ? p[gh * 64 + gw] : 0.f;
        }
    float tt[6][6];
    #pragma unroll
    for (int c = 0; c < 6; ++c) {
        float col[6], o[6];
        #pragma unroll
        for (int r = 0; r < 6; ++r) col[r] = d[r][c];
        btform(col, o);
        #pragma unroll
        for (int r = 0; r < 6; ++r) tt[r][c] = o[r];
    }
    #pragma unroll
    for (int r = 0; r < 6; ++r) {
        float o[6];
        btform(tt[r], o);
        #pragma unroll
        for (int s = 0; s < 6; ++s)
            sM[tl][r * 6 + s][ci_l] = o[s];
    }
    __syncthreads();

    // write out: 288 rows (xi,tl) x 32 ci, coalesced 128B per row
    #pragma unroll
    for (int r = 0; r < 36; ++r) {
        int slot = t + 256 * r;
        int row  = slot >> 5, lane = slot & 31;
        int xi = row >> 3, wtl = row & 7;
        float v = sM[wtl][xi][lane];
        float rem;
        u32 h = bfsplit(v, rem);
        __nv_bfloat16 lo = __float2bfloat16(rem);
        g_Vpk[((size_t)xi * NT2 + (img << 8) + tgrp * 8 + wtl) * CIN + cig * 32 + lane] =
            h | ((u32)__bfloat16_as_ushort(lo) << 16);
    }
}

// ---------------------------------------------------------------------------
// Repack U -> bf16 hi/lo in mma A-fragment order (validated R15).
// ---------------------------------------------------------------------------
template<int CO>
__global__ __launch_bounds__(256)
void repack_a()
{
    __shared__ float sUc[32][132];
    const float* U = Uptr<CO>();
    u32* Ah = Ahp<CO>();
    u32* Al = Alp<CO>();

    int c  = blockIdx.x;
    int cz = blockIdx.y;
    int xi = blockIdx.z;
    int t  = threadIdx.x;

    #pragma unroll
    for (int r = 0; r < 16; ++r) {
        int slot = t + 256 * r;
        int k = slot >> 7, co = slot & 127;
        sUc[k][co] = U[((size_t)xi * CIN + c * 32 + k) * CO + cz * 128 + co];
    }
    __syncthreads();

    size_t base = ((size_t)(xi * (CO / 128) + cz) * KCH + c) * 2048;
    #pragma unroll
    for (int r = 0; r < 8; ++r) {
        int slot = t + 256 * r;
        int lane = slot & 31, q = (slot >> 5) & 15, wm = slot >> 9;
        int kb = q >> 3, f = (q >> 2) & 1, reg = q & 3;
        int co = wm * 32 + f * 16 + (lane >> 2) + (reg & 1) * 8;
        int k  = kb * 16 + 2 * (lane & 3) + (reg >> 1) * 8;
        float r0, r1;
        u32 h0 = bfsplit(sUc[k][co], r0);
        u32 h1 = bfsplit(sUc[k + 1][co], r1);
        __nv_bfloat16 l0 = __float2bfloat16(r0);
        __nv_bfloat16 l1 = __float2bfloat16(r1);
        Ah[base + slot] = h0 | (h1 << 16);
        Al[base + slot] = (u32)__bfloat16_as_ushort(l0) |
                          ((u32)__bfloat16_as_ushort(l1) << 16);
    }
}

// ---------------------------------------------------------------------------
// GEMM via mma.sync (validated R15)
// ---------------------------------------------------------------------------
#define B_TILE 8192

template<int CO>
__global__ __launch_bounds__(256)
void gemm_mma()
{
    __shared__ u32 sB[2 * 2 * 2048];
    const u32 sb = smem_u32(sB);

    const u32* Ah = Ahp<CO>();
    const u32* Al = Alp<CO>();
    float*     M  = Mptr<CO>();

    const int t   = threadIdx.x;
    const int l   = t & 31;
    const int wid = t >> 5;
    const int wm  = wid & 3;
    const int wn  = wid >> 2;
    const int t0  = blockIdx.x * 128;
    const int cz  = blockIdx.y;
    const int xi  = blockIdx.z;

    float acc[2][8][4];
    #pragma unroll
    for (int f = 0; f < 2; ++f)
        #pragma unroll
        for (int nf = 0; nf < 8; ++nf)
            #pragma unroll
            for (int r = 0; r < 4; ++r) acc[f][nf][r] = 0.f;

    const size_t abase = ((size_t)(xi * (CO / 128) + cz) * KCH) * 2048 + wm * 512 + l;
    const u32* Vb = g_Vpk + (size_t)xi * NT2 * CIN;
    const u32 lm_base = sb + (u32)(wn * 4096 + ((l >> 3) & 1) * 128 + (l & 7) * 16);

    for (int c = 0; c < KCH; ++c) {
        const int buf = c & 1;
        const u32 bB = sb + (u32)(buf * 16384);

        #pragma unroll
        for (int rep = 0; rep < 4; ++rep) {
            int slot = t + rep * 256;
            int bn = slot >> 3, kq = slot & 7;
            uint4 v4 = *(const uint4*)&Vb[(size_t)(t0 + bn) * CIN + c * 32 + kq * 4];
            u32 h01 = (v4.x & 0xFFFFu) | (v4.y << 16);
            u32 l01 = (v4.x >> 16) | (v4.y & 0xFFFF0000u);
            u32 h23 = (v4.z & 0xFFFFu) | (v4.w << 16);
            u32 l23 = (v4.z >> 16) | (v4.w & 0xFFFF0000u);
            u32 ad = bB + (u32)(((bn >> 3) * 4 + (kq >> 1)) * 128 +
                                (bn & 7) * 16 + (kq & 1) * 8);
            asm volatile("st.shared.v2.b32 [%0], {%1,%2};" :: "r"(ad), "r"(h01), "r"(h23) : "memory");
            asm volatile("st.shared.v2.b32 [%0], {%1,%2};" :: "r"(ad + B_TILE), "r"(l01), "r"(l23) : "memory");
        }

        u32 ah[16], al[16];
        {
            const u32* aph = Ah + abase + (size_t)c * 2048;
            const u32* apl = Al + abase + (size_t)c * 2048;
            #pragma unroll
            for (int q = 0; q < 16; ++q) { ah[q] = aph[q * 32]; al[q] = apl[q * 32]; }
        }
        __syncthreads();

        const u32 lb = lm_base + (u32)(buf * 16384);
        #pragma unroll
        for (int kb = 0; kb < 2; ++kb) {
            #pragma unroll
            for (int nf = 0; nf < 8; ++nf) {
                u32 a = lb + (u32)(nf * 512 + kb * 256);
                u32 bh[2], bl_[2];
                ldmx2(bh[0], bh[1], a);
                ldmx2(bl_[0], bl_[1], a + B_TILE);
                #pragma unroll
                for (int f = 0; f < 2; ++f) {
                    const u32* a_h = ah + kb * 8 + f * 4;
                    const u32* a_l = al + kb * 8 + f * 4;
                    mma_bf16(acc[f][nf], a_h, bh);
                    mma_bf16(acc[f][nf], a_l, bh);
                    mma_bf16(acc[f][nf], a_h, bl_);
                }
            }
        }
        __syncthreads();
    }

    #pragma unroll
    for (int f = 0; f < 2; ++f) {
        int co = cz * 128 + wm * 32 + f * 16 + (l >> 2);
        #pragma unroll
        for (int nf = 0; nf < 8; ++nf) {
            int n0 = t0 + wn * 64 + nf * 8 + 2 * (l & 3);
            float* mb = M + ((size_t)xi * CO + co) * NT2 + n0;
            *(float2*)mb = make_float2(acc[f][nf][0], acc[f][nf][1]);
            *(float2*)(mb + 8 * (size_t)NT2) = make_float2(acc[f][nf][2], acc[f][nf][3]);
        }
    }
}

// ---------------------------------------------------------------------------
// Output transform Y = A^T M A (6x6 -> 4x4) + BN + ReLU -> NCHW
// ---------------------------------------------------------------------------
__device__ __forceinline__ void atform(const float* m, float* o)
{
    o[0] = m[0] + m[1] + m[2] + m[3] + m[4];
    o[1] = m[1] - m[2] + 2.f * (m[3] - m[4]);
    o[2] = m[1] + m[2] + 4.f * (m[3] + m[4]);
    o[3] = m[1] - m[2] + 8.f * (m[3] - m[4]) + m[5];
}

template<int CO, bool TO_SBUF>
__global__ void out_wino(const float* __restrict__ bg, const float* __restrict__ bb,
                         const float* __restrict__ bm, const float* __restrict__ bv,
                         float* __restrict__ out_ext)
{
    const float* M = Mptr<CO>();
    int co = blockIdx.y;
    int tg = blockIdx.x * 256 + threadIdx.x;

    float m[36];
    #pragma unroll
    for (int xi = 0; xi < 36; ++xi)
        m[xi] = M[((size_t)xi * CO + co) * NT2 + tg];

    float z[4][6];
    #pragma unroll
    for (int c = 0; c < 6; ++c) {
        float col[6] = {m[c], m[6 + c], m[12 + c], m[18 + c], m[24 + c], m[30 + c]};
        float o[4];
        atform(col, o);
        #pragma unroll
        for (int r = 0; r < 4; ++r) z[r][c] = o[r];
    }

    float sc = bg[co] * rsqrtf(bv[co] + 1e-5f);
    float bi = bb[co] - bm[co] * sc;

    int img = tg >> 8, tile = tg & 255;
    int ty = tile >> 4, tx = tile & 15;
    float* op = TO_SBUF ? g_sbuf : out_ext;
    float* ob = op + (((size_t)img * CO + co) * HW + 4 * ty) * HW + 4 * tx;

    #pragma unroll
    for (int r = 0; r < 4; ++r) {
        float y[4];
        atform(z[r], y);
        #pragma unroll
        for (int i = 0; i < 4; ++i) {
            float v = fmaf(y[i], sc, bi);
            y[i] = v > 0.f ? v : 0.f;
        }
        *(float4*)(ob + r * HW) = make_float4(y[0], y[1], y[2], y[3]);
    }
}

// ---------------------------------------------------------------------------
// Tail
// ---------------------------------------------------------------------------
__global__ void y2_kernel(const float* __restrict__ ce2)
{
    int nb = blockIdx.x;
    int n = nb >> 6, h = nb & 63, w = threadIdx.x;
    const float* p = ce2 + ((size_t)n * C2 * HW + h) * HW + w;
    float acc = 0.f;
    for (int c = 0; c < C2; ++c) {
        float v = p[(size_t)c * HW * HW];
        acc = fmaf(v, v, acc);
    }
    g_y2[(n * HW + h) * HW + w] = acc;
}

__global__ __launch_bounds__(512)
void wgt_kernel(const float* __restrict__ ce2)
{
    __shared__ float s_oth[8][5][68];
    __shared__ float s_acc[26][4][64];

    int nb = blockIdx.x;
    int n = nb >> 6, h = nb & 63;
    int t = threadIdx.x;
    int cg = t >> 6, w = t & 63;

    float acc[25];
    #pragma unroll
    for (int o = 0; o < 25; ++o) acc[o] = 0.f;
    float x2 = 0.f;

    const float* oth = ce2 + (size_t)n       * C2 * HW * HW;
    const float* c2  = ce2 + (size_t)(2 + n) * C2 * HW * HW;

    for (int c0 = 0; c0 < C2; c0 += 8) {
        __syncthreads();
        for (int e = t; e < 2720; e += 512) {
            int ec  = e / 340;
            int rem = e - ec * 340;
            int rr  = rem / 68;
            int ww  = rem - rr * 68;
            int gh  = h + rr - 2;
            int gw  = ww - 2;
            float v = 0.f;
            if ((unsigned)gh < 64u && (unsigned)gw < 64u)
                v = oth[((size_t)(c0 + ec) * HW + gh) * HW + gw];
            s_oth[ec][rr][ww] = v;
        }
        __syncthreads();

        float cv = c2[((size_t)(c0 + cg) * HW + h) * HW + w];
        x2 = fmaf(cv, cv, x2);
        #pragma unroll
        for (int o = 0; o < 25; ++o)
            acc[o] = fmaf(cv, s_oth[cg][o / 5][w + (o % 5)], acc[o]);
    }

    __syncthreads();
    if (cg >= 4) {
        #pragma unroll
        for (int o = 0; o < 25; ++o) s_acc[o][cg - 4][w] = acc[o];
        s_acc[25][cg - 4][w] = x2;
    }
    __syncthreads();
    if (cg < 4) {
        #pragma unroll
        for (int o = 0; o < 25; ++o) s_acc[o][cg][w] += acc[o];
        s_acc[25][cg][w] += x2;
    }
    __syncthreads();

    if (cg == 0) {
        float X2 = s_acc[25][0][w] + s_acc[25][1][w] + s_acc[25][2][w] + s_acc[25][3][w];
        float inv[25];
        #pragma unroll
        for (int o = 0; o < 25; ++o) {
            float cr = s_acc[o][0][w] + s_acc[o][1][w] + s_acc[o][2][w] + s_acc[o][3][w];
            int gh = h + (o / 5) - 2;
            int gw = w + (o % 5) - 2;
            float y2v = 1e20f;
            if ((unsigned)gh < 64u && (unsigned)gw < 64u)
                y2v = g_y2[(n * HW + gh) * HW + gw];
            float dist = X2 + y2v - 2.f * cr;
            inv[o] = 1.f / (dist + 1e-5f);
        }
        float m = inv[0];
        #pragma unroll
        for (int o = 1; o < 25; ++o) m = fmaxf(m, inv[o]);
        float s = 0.f;
        #pragma unroll
        for (int o = 0; o < 25; ++o) { inv[o] = expf(inv[o] - m); s += inv[o]; }
        float rs = 1.f / s;
        #pragma unroll
        for (int o = 0; o < 25; ++o)
            g_wgt[((o * NPAIR + n) * HW + h) * HW + w] = inv[o] * rs;
    }
}

__global__ __launch_bounds__(512)
void warp_kernel()
{
    __shared__ float s_w25[25][64];
    __shared__ float s_oth[8][5][68];

    int nb = blockIdx.x;
    int n = nb >> 6, h = nb & 63;
    int t = threadIdx.x;

    for (int e = t; e < 1600; e += 512) {
        int o = e >> 6, ww = e & 63;
        s_w25[o][ww] = g_wgt[((o * NPAIR + n) * HW + h) * HW + ww];
    }

    const float* oth = g_sbuf + (size_t)n       * C1 * HW * HW;
    const float* cim = g_sbuf + (size_t)(2 + n) * C1 * HW * HW;
    int cc = t >> 6, w = t & 63;

    for (int c0 = 0; c0 < C1; c0 += 8) {
        __syncthreads();
        for (int e = t; e < 2720; e += 512) {
            int ec  = e / 340;
            int rem = e - ec * 340;
            int rr  = rem / 68;
            int ww  = rem - rr * 68;
            int gh  = h + rr - 2;
            int gw  = ww - 2;
            float v = 0.f;
            if ((unsigned)gh < 64u && (unsigned)gw < 64u)
                v = oth[((size_t)(c0 + ec) * HW + gh) * HW + gw];
            s_oth[ec][rr][ww] = v;
        }
        __syncthreads();

        float civ = cim[((size_t)(c0 + cc) * HW + h) * HW + w];
        float a = 0.f;
        #pragma unroll
        for (int o = 0; o < 25; ++o)
            a = fmaf(s_w25[o][w], s_oth[cc][o / 5][w + (o % 5)], a);
        float res = 0.5f * (civ + a * (1.0f / 25.0f));
        g_final[(((size_t)n * HW + h) * HW + w) * C1 + c0 + cc] = res;
    }
}

__global__ void wt_kernel(const float* __restrict__ lw)
{
    int o = blockIdx.x, c = threadIdx.x;
    g_WT[c * NCLS + o] = lw[o * 256 + c];
}

__global__ __launch_bounds__(128)
void head_kernel(const float* __restrict__ lb, float* __restrict__ xout)
{
    __shared__ float s_x[8][256];
    __shared__ float s_red[8][132];
    __shared__ float s_mx[8], s_ls[8];

    int pg = blockIdx.x;
    int t  = threadIdx.x;
    int l  = t & 31, wid = t >> 5;

    for (int e = t; e < 2048; e += 128) {
        int pp = e >> 8, c = e & 255;
        s_x[pp][c] = g_final[((size_t)pg * 8 + pp) * 256 + c];
    }
    __syncthreads();

    float acc[8];
    #pragma unroll
    for (int pp = 0; pp < 8; ++pp) acc[pp] = 0.f;

    if (t < NCLS) {
        for (int c = 0; c < 256; ++c) {
            float wv = g_WT[c * NCLS + t];
            #pragma unroll
            for (int pp = 0; pp < 8; ++pp)
                acc[pp] = fmaf(s_x[pp][c], wv, acc[pp]);
        }
        float bias = lb[t];
        #pragma unroll
        for (int pp = 0; pp < 8; ++pp) acc[pp] += bias;
    }

    #pragma unroll
    for (int pp = 0; pp < 8; ++pp)
        s_red[pp][t] = (t < NCLS) ? acc[pp] : -3.4e38f;
    __syncthreads();

    #pragma unroll
    for (int pp0 = 0; pp0 < 2; ++pp0) {
        int pp = wid + pp0 * 4;
        float v = fmaxf(fmaxf(s_red[pp][l], s_red[pp][l + 32]),
                        fmaxf(s_red[pp][l + 64], s_red[pp][l + 96]));
        #pragma unroll
        for (int s = 16; s > 0; s >>= 1)
            v = fmaxf(v, __shfl_xor_sync(0xFFFFFFFFu, v, s));
        if (l == 0) s_mx[pp] = v;
    }
    __syncthreads();

    #pragma unroll
    for (int pp = 0; pp < 8; ++pp)
        s_red[pp][t] = (t < NCLS) ? expf(acc[pp] - s_mx[pp]) : 0.f;
    __syncthreads();

    #pragma unroll
    for (int pp0 = 0; pp0 < 2; ++pp0) {
        int pp = wid + pp0 * 4;
        float v = s_red[pp][l] + s_red[pp][l + 32] + s_red[pp][l + 64] + s_red[pp][l + 96];
        #pragma unroll
        for (int s = 16; s > 0; s >>= 1)
            v += __shfl_xor_sync(0xFFFFFFFFu, v, s);
        if (l == 0) s_ls[pp] = s_mx[pp] + logf(v);
    }
    __syncthreads();

    if (t < NCLS) {
        #pragma unroll
        for (int pp = 0; pp < 8; ++pp) {
            int pix = pg * 8 + pp;
            int n = pix >> 12, h = (pix >> 6) & 63, w = pix & 63;
            xout[(((size_t)n * NCLS + t) * HW + h) * HW + w] = acc[pp] - s_ls[pp];
        }
    }
}

// ---------------------------------------------------------------------------
extern "C" void kernel_launch(void* const* d_in, const int* in_sizes, int n_in,
                              void* d_out, int out_size)
{
    const float* clip  = (const float*)d_in[0];
    const float* embW  = (const float*)d_in[2];
    const float* eg    = (const float*)d_in[3];
    const float* eb    = (const float*)d_in[4];
    const float* em    = (const float*)d_in[5];
    const float* ev    = (const float*)d_in[6];
    const float* emb2W = (const float*)d_in[7];
    const float* e2g   = (const float*)d_in[8];
    const float* e2b   = (const float*)d_in[9];
    const float* e2m   = (const float*)d_in[10];
    const float* e2v   = (const float*)d_in[11];
    const float* lastW = (const float*)d_in[12];
    const float* lastb = (const float*)d_in[13];

    float* xout = (float*)d_out;
    float* ce2  = (float*)d_out + X_ELEMS;

    prep_u<C1><<<CIN, C1>>>(embW);
    prep_u<C2><<<CIN, C2>>>(emb2W);
    prep_v_pk<<<dim3(32, 16, NIMG), 256>>>(clip);

    repack_a<C1><<<dim3(KCH, 2, 36), 256>>>();
    repack_a<C2><<<dim3(KCH, 1, 36), 256>>>();

    gemm_mma<C2><<<dim3(NT2 / 128, 1, 36), 256>>>();
    gemm_mma<C1><<<dim3(NT2 / 128, 2, 36), 256>>>();

    out_wino<C2, false><<<dim3(NT2 / 256, C2), 256>>>(e2g, e2b, e2m, e2v, ce2);
    out_wino<C1, true ><<<dim3(NT2 / 256, C1), 256>>>(eg, eb, em, ev, nullptr);

    y2_kernel <<<NPAIR * HW, 64>>>(ce2);
    wgt_kernel<<<NPAIR * HW, 512>>>(ce2);
    warp_kernel<<<NPAIR * HW, 512>>>();
    wt_kernel  <<<NCLS, 256>>>(lastW);
    head_kernel<<<(NPAIR * HW * HW) / 8, 128>>>(lastb, xout);
}